// round 1
// baseline (speedup 1.0000x reference)
#include <cuda_runtime.h>
#include <math.h>

// Problem dims
#define BB 2
#define TT 2048
#define HIDN 1024
#define NH 8
#define DKK 128
#define NROWS (BB*TT)      // 4096
#define TCH 128            // chunk length
#define NCHUNK (TT/TCH)    // 16 per batch
#define NBH (BB*NH)        // 16

// -------- scratch (static device globals; no allocation) --------
__device__ float g_Q[NROWS*HIDN];
__device__ float g_EK[NROWS*HIDN];     // raw k, then exp(k) in place
__device__ float g_V[NROWS*HIDN];
__device__ float g_G1[NROWS*128];
__device__ float g_gate[NROWS*HIDN];
__device__ float g_QH[NROWS*HIDN];     // q / A_t * scale
__device__ float g_O[NROWS*HIDN];
__device__ float g_U[NROWS*HIDN];
__device__ float g_Asum[NBH*NCHUNK*DKK];          // per-chunk colsum -> exclusive prefix
__device__ float g_Cc[NBH*NCHUNK*DKK*DKK];        // per-chunk K^T V -> exclusive prefix

// 8x8 microkernel on split fragments (rows {ty*4..+3, 64+ty*4..+3})
#define MICRO_FMA(Aptr, Bptr, kk) do {                                    \
    float4 a0 = *(const float4*)&(Aptr)[(kk)*132 + ty*4];                 \
    float4 a1 = *(const float4*)&(Aptr)[(kk)*132 + 64 + ty*4];            \
    float4 b0 = *(const float4*)&(Bptr)[(kk)*132 + tx*4];                 \
    float4 b1 = *(const float4*)&(Bptr)[(kk)*132 + 64 + tx*4];            \
    float av[8] = {a0.x,a0.y,a0.z,a0.w,a1.x,a1.y,a1.z,a1.w};              \
    float bv[8] = {b0.x,b0.y,b0.z,b0.w,b1.x,b1.y,b1.z,b1.w};              \
    _Pragma("unroll") for (int ii=0; ii<8; ii++)                          \
      _Pragma("unroll") for (int jj=0; jj<8; jj++)                        \
        acc[ii][jj] += av[ii]*bv[jj];                                     \
} while(0)

__device__ __forceinline__ int fragmap(int idx, int t4) {
    return (idx < 4) ? (t4*4 + idx) : (64 + t4*4 + idx - 4);
}

// -------- generic NT GEMM: C[M,N] = A[M,K] * B[N,K]^T, optional SiLU --------
template<int ACT>
__global__ __launch_bounds__(256)
void gemm_nt(const float* __restrict__ A, const float* __restrict__ B,
             float* __restrict__ C, int M, int N, int K) {
    __shared__ float As[16*132];
    __shared__ float Bs[16*132];
    const int tid = threadIdx.x;
    const int tx = tid & 15, ty = tid >> 4;
    const int rowA = blockIdx.y * 128;
    const int rowB = blockIdx.x * 128;
    const int lr = tid >> 2;          // 0..63
    const int lk = (tid & 3) << 2;    // 0,4,8,12
    float acc[8][8];
#pragma unroll
    for (int i = 0; i < 8; i++)
#pragma unroll
        for (int j = 0; j < 8; j++) acc[i][j] = 0.f;

    for (int k0 = 0; k0 < K; k0 += 16) {
#pragma unroll
        for (int hh = 0; hh < 2; hh++) {
            int r = lr + (hh << 6);
            float4 va = *(const float4*)(A + (size_t)(rowA + r)*K + k0 + lk);
            As[(lk+0)*132 + r] = va.x; As[(lk+1)*132 + r] = va.y;
            As[(lk+2)*132 + r] = va.z; As[(lk+3)*132 + r] = va.w;
            float4 vb = *(const float4*)(B + (size_t)(rowB + r)*K + k0 + lk);
            Bs[(lk+0)*132 + r] = vb.x; Bs[(lk+1)*132 + r] = vb.y;
            Bs[(lk+2)*132 + r] = vb.z; Bs[(lk+3)*132 + r] = vb.w;
        }
        __syncthreads();
#pragma unroll
        for (int k = 0; k < 16; k++) MICRO_FMA(As, Bs, k);
        __syncthreads();
    }
#pragma unroll
    for (int i = 0; i < 8; i++) {
        int m = rowA + fragmap(i, ty);
        float v[8];
#pragma unroll
        for (int j = 0; j < 8; j++) {
            v[j] = acc[i][j];
            if (ACT == 1) v[j] = v[j] / (1.f + expf(-v[j]));
        }
        float4 s0 = make_float4(v[0], v[1], v[2], v[3]);
        float4 s1 = make_float4(v[4], v[5], v[6], v[7]);
        *(float4*)(C + (size_t)m*N + rowB + tx*4)      = s0;
        *(float4*)(C + (size_t)m*N + rowB + 64 + tx*4) = s1;
    }
}

// -------- pass A: exp(k) in place, per-chunk colsum, per-chunk C = EK^T V --------
__global__ __launch_bounds__(256)
void chunk_stats() {
    const int c = blockIdx.x, bh = blockIdx.y;
    const int b = bh >> 3, h = bh & 7;
    const int base = b*TT + c*TCH;
    const int hoff = h*DKK;
    __shared__ float EKs[8*132];
    __shared__ float Vs[8*132];
    __shared__ float red[8*128];
    const int tid = threadIdx.x;
    const int tx = tid & 15, ty = tid >> 4;
    const int trow = tid >> 5;         // 0..7
    const int col = (tid & 31) << 2;   // 0..124
    float acc[8][8];
#pragma unroll
    for (int i = 0; i < 8; i++)
#pragma unroll
        for (int j = 0; j < 8; j++) acc[i][j] = 0.f;
    float ps0 = 0.f, ps1 = 0.f, ps2 = 0.f, ps3 = 0.f;

    for (int tt = 0; tt < TCH/8; tt++) {
        int row = base + tt*8 + trow;
        float4 kv = *(const float4*)(g_EK + (size_t)row*HIDN + hoff + col);
        kv.x = expf(kv.x); kv.y = expf(kv.y); kv.z = expf(kv.z); kv.w = expf(kv.w);
        *(float4*)(g_EK + (size_t)row*HIDN + hoff + col) = kv;   // overwrite in place
        ps0 += kv.x; ps1 += kv.y; ps2 += kv.z; ps3 += kv.w;
        *(float4*)&EKs[trow*132 + col] = kv;
        float4 vv = *(const float4*)(g_V + (size_t)row*HIDN + hoff + col);
        *(float4*)&Vs[trow*132 + col] = vv;
        __syncthreads();
#pragma unroll
        for (int k = 0; k < 8; k++) MICRO_FMA(EKs, Vs, k);   // rows=dk, cols=dv, k=t
        __syncthreads();
    }
    // deterministic colsum reduction
    red[trow*128 + col + 0] = ps0; red[trow*128 + col + 1] = ps1;
    red[trow*128 + col + 2] = ps2; red[trow*128 + col + 3] = ps3;
    __syncthreads();
    if (tid < DKK) {
        float s = 0.f;
#pragma unroll
        for (int r = 0; r < 8; r++) s += red[r*128 + tid];
        g_Asum[(bh*NCHUNK + c)*DKK + tid] = s;
    }
    size_t cb = ((size_t)(bh*NCHUNK + c))*DKK*DKK;
#pragma unroll
    for (int i = 0; i < 8; i++) {
        int dk = fragmap(i, ty);
        float4 s0 = make_float4(acc[i][0], acc[i][1], acc[i][2], acc[i][3]);
        float4 s1 = make_float4(acc[i][4], acc[i][5], acc[i][6], acc[i][7]);
        *(float4*)(g_Cc + cb + (size_t)dk*DKK + tx*4)      = s0;
        *(float4*)(g_Cc + cb + (size_t)dk*DKK + 64 + tx*4) = s1;
    }
}

// -------- pass B: exclusive prefixes across chunks --------
__global__ void scan_asum() {
    int bh = blockIdx.x, dk = threadIdx.x;
    float run = 0.f;
    for (int c = 0; c < NCHUNK; c++) {
        int i = (bh*NCHUNK + c)*DKK + dk;
        float v = g_Asum[i]; g_Asum[i] = run; run += v;
    }
}
__global__ void scan_cc() {
    int bh = blockIdx.y;
    int idx = blockIdx.x*256 + threadIdx.x;   // 0..16383
    float run = 0.f;
    for (int c = 0; c < NCHUNK; c++) {
        size_t p = ((size_t)(bh*NCHUNK + c))*(DKK*DKK) + idx;
        float v = g_Cc[p]; g_Cc[p] = run; run += v;
    }
}

// -------- pass C1: Qhat = silu(q)/A_t * scale --------
__global__ void compute_qhat() {
    const int c = blockIdx.x, bh = blockIdx.y;
    const int b = bh >> 3, h = bh & 7;
    const int base = b*TT + c*TCH;
    const int dk = threadIdx.x;   // 128
    const float scale = 0.08838834764831845f;  // 128^-0.5
    float run = g_Asum[(bh*NCHUNK + c)*DKK + dk];  // exclusive chunk prefix
    for (int t = 0; t < TCH; t++) {
        size_t gi = (size_t)(base + t)*HIDN + h*DKK + dk;
        run += g_EK[gi];
        g_QH[gi] = g_Q[gi] / run * scale;
    }
}

// -------- pass C2: O = tril(QH EK^T) V + QH Cex --------
__global__ __launch_bounds__(256)
void chunk_out() {
    extern __shared__ float sm[];
    float* Ps  = sm;                    // 128*132
    float* Asm = sm + 128*132;          // 8*132
    float* Bsm = Asm + 8*132;           // 8*132
    const int c = blockIdx.x, bh = blockIdx.y;
    const int b = bh >> 3, h = bh & 7;
    const int base = b*TT + c*TCH;
    const int hoff = h*DKK;
    const int tid = threadIdx.x;
    const int tx = tid & 15, ty = tid >> 4;
    const int lr = tid >> 1;           // 0..127
    const int lk = (tid & 1) << 2;     // 0 or 4
    const int trow = tid >> 5, col = (tid & 31) << 2;
    float acc[8][8];
#pragma unroll
    for (int i = 0; i < 8; i++)
#pragma unroll
        for (int j = 0; j < 8; j++) acc[i][j] = 0.f;

    // Stage 1: P = QH * EK^T (reduction over dk)
    for (int kt = 0; kt < DKK/8; kt++) {
        float4 va = *(const float4*)(g_QH + (size_t)(base+lr)*HIDN + hoff + kt*8 + lk);
        Asm[(lk+0)*132 + lr] = va.x; Asm[(lk+1)*132 + lr] = va.y;
        Asm[(lk+2)*132 + lr] = va.z; Asm[(lk+3)*132 + lr] = va.w;
        float4 vb = *(const float4*)(g_EK + (size_t)(base+lr)*HIDN + hoff + kt*8 + lk);
        Bsm[(lk+0)*132 + lr] = vb.x; Bsm[(lk+1)*132 + lr] = vb.y;
        Bsm[(lk+2)*132 + lr] = vb.z; Bsm[(lk+3)*132 + lr] = vb.w;
        __syncthreads();
#pragma unroll
        for (int k = 0; k < 8; k++) MICRO_FMA(Asm, Bsm, k);
        __syncthreads();
    }
    // causal mask into Ps
#pragma unroll
    for (int i = 0; i < 8; i++) {
        int t = fragmap(i, ty);
#pragma unroll
        for (int j = 0; j < 8; j++) {
            int s = fragmap(j, tx);
            Ps[t*132 + s] = (s <= t) ? acc[i][j] : 0.f;
        }
    }
    __syncthreads();
#pragma unroll
    for (int i = 0; i < 8; i++)
#pragma unroll
        for (int j = 0; j < 8; j++) acc[i][j] = 0.f;

    // Stage 2a: intra O += P * V (reduction over s)
    for (int st = 0; st < TCH/8; st++) {
        float4 vv = *(const float4*)(g_V + (size_t)(base + st*8 + trow)*HIDN + hoff + col);
        *(float4*)&Bsm[trow*132 + col] = vv;
        __syncthreads();
#pragma unroll
        for (int k = 0; k < 8; k++) {
            int s = st*8 + k;
            float av[8];
#pragma unroll
            for (int i = 0; i < 4; i++) av[i]   = Ps[(ty*4 + i)*132 + s];
#pragma unroll
            for (int i = 0; i < 4; i++) av[4+i] = Ps[(64 + ty*4 + i)*132 + s];
            float4 b0 = *(const float4*)&Bsm[k*132 + tx*4];
            float4 b1 = *(const float4*)&Bsm[k*132 + 64 + tx*4];
            float bv[8] = {b0.x,b0.y,b0.z,b0.w,b1.x,b1.y,b1.z,b1.w};
#pragma unroll
            for (int i = 0; i < 8; i++)
#pragma unroll
                for (int j = 0; j < 8; j++) acc[i][j] += av[i]*bv[j];
        }
        __syncthreads();
    }

    // Stage 2b: inter O += QH * Cex (reduction over dk)
    size_t cb = ((size_t)(bh*NCHUNK + c))*DKK*DKK;
    for (int kt = 0; kt < DKK/8; kt++) {
        float4 va = *(const float4*)(g_QH + (size_t)(base+lr)*HIDN + hoff + kt*8 + lk);
        Asm[(lk+0)*132 + lr] = va.x; Asm[(lk+1)*132 + lr] = va.y;
        Asm[(lk+2)*132 + lr] = va.z; Asm[(lk+3)*132 + lr] = va.w;
        float4 vb = *(const float4*)(g_Cc + cb + (size_t)(kt*8 + trow)*DKK + col);
        *(float4*)&Bsm[trow*132 + col] = vb;
        __syncthreads();
#pragma unroll
        for (int k = 0; k < 8; k++) MICRO_FMA(Asm, Bsm, k);
        __syncthreads();
    }

    // write O
#pragma unroll
    for (int i = 0; i < 8; i++) {
        int t = fragmap(i, ty);
        float4 s0 = make_float4(acc[i][0], acc[i][1], acc[i][2], acc[i][3]);
        float4 s1 = make_float4(acc[i][4], acc[i][5], acc[i][6], acc[i][7]);
        *(float4*)(g_O + (size_t)(base+t)*HIDN + hoff + tx*4)      = s0;
        *(float4*)(g_O + (size_t)(base+t)*HIDN + hoff + 64 + tx*4) = s1;
    }
}

// -------- epilogue: RMSNorm(o) * w * gate * sigmoid(gate) --------
__global__ __launch_bounds__(256)
void epilogue_k(const float* __restrict__ gnw) {
    __shared__ float red[256];
    const int n = blockIdx.x, tid = threadIdx.x;
    float4 ov = *((const float4*)(g_O + (size_t)n*HIDN) + tid);
    float ss = ov.x*ov.x + ov.y*ov.y + ov.z*ov.z + ov.w*ov.w;
    red[tid] = ss;
    __syncthreads();
    for (int s = 128; s > 0; s >>= 1) {
        if (tid < s) red[tid] += red[tid + s];
        __syncthreads();
    }
    float rms = rsqrtf(red[0] * (1.f/HIDN) + 1e-5f);
    float4 gv = *((const float4*)(g_gate + (size_t)n*HIDN) + tid);
    float4 wv = *((const float4*)gnw + tid);
    float4 u;
    u.x = ov.x*rms*wv.x * gv.x / (1.f + expf(-gv.x));
    u.y = ov.y*rms*wv.y * gv.y / (1.f + expf(-gv.y));
    u.z = ov.z*rms*wv.z * gv.z / (1.f + expf(-gv.z));
    u.w = ov.w*rms*wv.w * gv.w / (1.f + expf(-gv.w));
    *((float4*)(g_U + (size_t)n*HIDN) + tid) = u;
}

extern "C" void kernel_launch(void* const* d_in, const int* in_sizes, int n_in,
                              void* d_out, int out_size) {
    const float* x   = (const float*)d_in[0];
    const float* Wq  = (const float*)d_in[1];
    const float* Wk  = (const float*)d_in[2];
    const float* Wv  = (const float*)d_in[3];
    const float* Wg1 = (const float*)d_in[4];
    const float* Wg2 = (const float*)d_in[5];
    const float* gnw = (const float*)d_in[6];
    const float* Wo  = (const float*)d_in[7];
    float* out = (float*)d_out;

    float *Q, *EK, *V, *G1, *GATE, *U;
    cudaGetSymbolAddress((void**)&Q,    g_Q);
    cudaGetSymbolAddress((void**)&EK,   g_EK);
    cudaGetSymbolAddress((void**)&V,    g_V);
    cudaGetSymbolAddress((void**)&G1,   g_G1);
    cudaGetSymbolAddress((void**)&GATE, g_gate);
    cudaGetSymbolAddress((void**)&U,    g_U);

    const int CO_SMEM = (128*132 + 2*8*132) * 4;  // 76032 B
    cudaFuncSetAttribute(chunk_out, cudaFuncAttributeMaxDynamicSharedMemorySize, CO_SMEM);

    dim3 blk(256);
    gemm_nt<1><<<dim3(8,32), blk>>>(x, Wq, Q, NROWS, HIDN, HIDN);       // silu(x Wq^T)
    gemm_nt<0><<<dim3(8,32), blk>>>(x, Wk, EK, NROWS, HIDN, HIDN);
    gemm_nt<0><<<dim3(8,32), blk>>>(x, Wv, V, NROWS, HIDN, HIDN);
    gemm_nt<0><<<dim3(1,32), blk>>>(x, Wg1, G1, NROWS, 128, HIDN);
    gemm_nt<0><<<dim3(8,32), blk>>>(G1, Wg2, GATE, NROWS, HIDN, 128);
    chunk_stats<<<dim3(NCHUNK, NBH), blk>>>();
    scan_asum<<<NBH, DKK>>>();
    scan_cc<<<dim3(64, NBH), 256>>>();
    compute_qhat<<<dim3(NCHUNK, NBH), DKK>>>();
    chunk_out<<<dim3(NCHUNK, NBH), blk, CO_SMEM>>>();
    epilogue_k<<<NROWS, blk>>>(gnw);
    gemm_nt<0><<<dim3(8,32), blk>>>(U, Wo, out, NROWS, HIDN, HIDN);
}

// round 3
// speedup vs baseline: 1.7273x; 1.7273x over previous
#include <cuda_runtime.h>
#include <cuda_bf16.h>
#include <cstdint>
#include <math.h>

// Problem dims
#define BB 2
#define TT 2048
#define HIDN 1024
#define NH 8
#define DKK 128
#define NROWS (BB*TT)      // 4096
#define TCH 128            // chunk length
#define NCHUNK (TT/TCH)    // 16 per batch
#define NBH (BB*NH)        // 16

#define SMEM_SWZ(off) ((off) ^ (((off) >> 3) & 0x70))

// -------- scratch (static device globals; no allocation) --------
__device__ float g_Q[NROWS*HIDN];
__device__ float g_EK[NROWS*HIDN];     // raw k, then exp(k) in place
__device__ float g_V[NROWS*HIDN];
__device__ float g_G1[NROWS*128];
__device__ float g_gate[NROWS*HIDN];
__device__ float g_QH[NROWS*HIDN];     // q / A_t * scale
__device__ float g_O[NROWS*HIDN];
__device__ float g_U[NROWS*HIDN];
__device__ float g_Asum[NBH*NCHUNK*DKK];
__device__ float g_Cc[NBH*NCHUNK*DKK*DKK];

// ================= mma.sync helpers =================
__device__ __forceinline__ uint32_t smem_u32(const void* p) {
    uint32_t a;
    asm("{ .reg .u64 t; cvta.to.shared.u64 t, %1; cvt.u32.u64 %0, t; }" : "=r"(a) : "l"(p));
    return a;
}
__device__ __forceinline__ void ldsm4(uint32_t* r, uint32_t addr) {
    asm volatile("ldmatrix.sync.aligned.m8n8.x4.shared.b16 {%0,%1,%2,%3}, [%4];"
        : "=r"(r[0]), "=r"(r[1]), "=r"(r[2]), "=r"(r[3]) : "r"(addr));
}
__device__ __forceinline__ void mma_bf16(float* d, const uint32_t* a, const uint32_t* b) {
    asm volatile("mma.sync.aligned.m16n8k16.row.col.f32.bf16.bf16.f32 "
        "{%0,%1,%2,%3}, {%4,%5,%6,%7}, {%8,%9}, {%0,%1,%2,%3};"
        : "+f"(d[0]), "+f"(d[1]), "+f"(d[2]), "+f"(d[3])
        : "r"(a[0]), "r"(a[1]), "r"(a[2]), "r"(a[3]), "r"(b[0]), "r"(b[1]));
}

// fp32 -> (hi, lo) bf16 pairs
__device__ __forceinline__ void cvt4(float4 v, uint2& hi, uint2& lo) {
    __nv_bfloat16 h0 = __float2bfloat16_rn(v.x);
    __nv_bfloat16 h1 = __float2bfloat16_rn(v.y);
    __nv_bfloat16 h2 = __float2bfloat16_rn(v.z);
    __nv_bfloat16 h3 = __float2bfloat16_rn(v.w);
    float r0 = v.x - __bfloat162float(h0);
    float r1 = v.y - __bfloat162float(h1);
    float r2 = v.z - __bfloat162float(h2);
    float r3 = v.w - __bfloat162float(h3);
    __nv_bfloat162 hp0 = __halves2bfloat162(h0, h1);
    __nv_bfloat162 hp1 = __halves2bfloat162(h2, h3);
    __nv_bfloat162 lp0 = __halves2bfloat162(__float2bfloat16_rn(r0), __float2bfloat16_rn(r1));
    __nv_bfloat162 lp1 = __halves2bfloat162(__float2bfloat16_rn(r2), __float2bfloat16_rn(r3));
    hi.x = *(uint32_t*)&hp0; hi.y = *(uint32_t*)&hp1;
    lo.x = *(uint32_t*)&lp0; lo.y = *(uint32_t*)&lp1;
}

// ======== tensor-core (HMMA) GEMM: C[M,N] = A[M,K] B[N,K]^T, split bf16 ======
// grid (N/128, M/128), 256 thr. BK=64 fp32 per stage, double-buffered.
// Stage layout (bytes): Ahi[16K] Alo[16K] Bhi[16K] Blo[16K] => 64KB/stage.
#define SG_AHI 0
#define SG_ALO 16384
#define SG_BHI 32768
#define SG_BLO 49152
#define SG_STRIDE 65536
#define GEMM_SMEM (2*SG_STRIDE + 1024)

__device__ __forceinline__ void fill_stage(char* sbase, const float* __restrict__ A,
                                           const float* __restrict__ B,
                                           int rowA, int rowB, int K, int k0, int tid) {
#pragma unroll
    for (int t = 0; t < 8; t++) {
        int idx = t * 256 + tid;          // 0..2047
        int r = idx >> 4;                  // 0..127
        int c4 = (idx & 15) << 2;          // float col 0..60
        uint32_t off = SMEM_SWZ((uint32_t)(r * 128 + c4 * 2));
        float4 va = *(const float4*)(A + (size_t)(rowA + r) * K + k0 + c4);
        uint2 hi, lo; cvt4(va, hi, lo);
        *(uint2*)(sbase + SG_AHI + off) = hi;
        *(uint2*)(sbase + SG_ALO + off) = lo;
        float4 vb = *(const float4*)(B + (size_t)(rowB + r) * K + k0 + c4);
        cvt4(vb, hi, lo);
        *(uint2*)(sbase + SG_BHI + off) = hi;
        *(uint2*)(sbase + SG_BLO + off) = lo;
    }
}

template<int ACT>
__global__ __launch_bounds__(256, 1)
void gemm_mma(const float* __restrict__ A, const float* __restrict__ B,
              float* __restrict__ C, int M, int N, int K) {
    extern __shared__ char dynsm[];
    char* tile = (char*)((((uintptr_t)dynsm) + 1023) & ~(uintptr_t)1023);
    const uint32_t tile_sa = smem_u32(tile);

    const int tid = threadIdx.x;
    const int wid = tid >> 5;
    const int l = tid & 31;
    const int warp_m = wid >> 1;       // 0..3
    const int warp_n = wid & 1;        // 0..1
    const int rowA = blockIdx.y * 128;
    const int rowB = blockIdx.x * 128;

    float acc[2][8][4];
#pragma unroll
    for (int mf = 0; mf < 2; mf++)
#pragma unroll
        for (int nf = 0; nf < 8; nf++)
#pragma unroll
            for (int j = 0; j < 4; j++) acc[mf][nf][j] = 0.f;

    // lane-invariant pieces of ldmatrix addresses
    const int a_row = warp_m * 32 + (l & 15);      // + mf*16
    const int a_kb  = (l >> 4) * 16;               // khalf byte offset
    const int b_row = warp_n * 64 + (l & 7) + ((l >> 4) & 1) * 8;  // + nf2*16
    const int b_kb  = ((l >> 3) & 1) * 16;

    const int nk = K >> 6;
    fill_stage(tile, A, B, rowA, rowB, K, 0, tid);
    __syncthreads();

    for (int kb = 0; kb < nk; kb++) {
        if (kb + 1 < nk)
            fill_stage(tile + ((kb + 1) & 1) * SG_STRIDE, A, B, rowA, rowB, K, (kb + 1) << 6, tid);

        const uint32_t st = tile_sa + (kb & 1) * SG_STRIDE;
#pragma unroll
        for (int ks = 0; ks < 4; ks++) {
            const int koff = ks * 32;
            uint32_t Ah[2][4], Al[2][4], Bh[4][4], Bl[4][4];
#pragma unroll
            for (int mf = 0; mf < 2; mf++) {
                uint32_t ro = SMEM_SWZ((uint32_t)((a_row + mf * 16) * 128 + koff + a_kb));
                ldsm4(Ah[mf], st + SG_AHI + ro);
                ldsm4(Al[mf], st + SG_ALO + ro);
            }
#pragma unroll
            for (int nf2 = 0; nf2 < 4; nf2++) {
                uint32_t ro = SMEM_SWZ((uint32_t)((b_row + nf2 * 16) * 128 + koff + b_kb));
                ldsm4(Bh[nf2], st + SG_BHI + ro);
                ldsm4(Bl[nf2], st + SG_BLO + ro);
            }
#pragma unroll
            for (int mf = 0; mf < 2; mf++)
#pragma unroll
                for (int nf = 0; nf < 8; nf++) {
                    const int nf2 = nf >> 1, ho = (nf & 1) * 2;
                    mma_bf16(acc[mf][nf], Ah[mf], &Bh[nf2][ho]);
                    mma_bf16(acc[mf][nf], Ah[mf], &Bl[nf2][ho]);
                    mma_bf16(acc[mf][nf], Al[mf], &Bh[nf2][ho]);
                }
        }
        __syncthreads();
    }

    // epilogue: D frag: d0,d1 -> (row l>>2, col 2*(l&3)+{0,1}); d2,d3 -> row+8
#pragma unroll
    for (int mf = 0; mf < 2; mf++)
#pragma unroll
        for (int nf = 0; nf < 8; nf++) {
            int r0 = rowA + warp_m * 32 + mf * 16 + (l >> 2);
            int cc = rowB + warp_n * 64 + nf * 8 + (l & 3) * 2;
            float v0 = acc[mf][nf][0], v1 = acc[mf][nf][1];
            float v2 = acc[mf][nf][2], v3 = acc[mf][nf][3];
            if (ACT == 1) {
                v0 = v0 / (1.f + expf(-v0));
                v1 = v1 / (1.f + expf(-v1));
                v2 = v2 / (1.f + expf(-v2));
                v3 = v3 / (1.f + expf(-v3));
            }
            *(float2*)(C + (size_t)r0 * N + cc)       = make_float2(v0, v1);
            *(float2*)(C + (size_t)(r0 + 8) * N + cc) = make_float2(v2, v3);
        }
}

// ================= attention kernels (SIMT fp32, unchanged) ==================
#define MICRO_FMA(Aptr, Bptr, kk) do {                                    \
    float4 a0 = *(const float4*)&(Aptr)[(kk)*132 + ty*4];                 \
    float4 a1 = *(const float4*)&(Aptr)[(kk)*132 + 64 + ty*4];            \
    float4 b0 = *(const float4*)&(Bptr)[(kk)*132 + tx*4];                 \
    float4 b1 = *(const float4*)&(Bptr)[(kk)*132 + 64 + tx*4];            \
    float av[8] = {a0.x,a0.y,a0.z,a0.w,a1.x,a1.y,a1.z,a1.w};              \
    float bv[8] = {b0.x,b0.y,b0.z,b0.w,b1.x,b1.y,b1.z,b1.w};              \
    _Pragma("unroll") for (int ii=0; ii<8; ii++)                          \
      _Pragma("unroll") for (int jj=0; jj<8; jj++)                        \
        acc[ii][jj] += av[ii]*bv[jj];                                     \
} while(0)

__device__ __forceinline__ int fragmap(int idx, int t4) {
    return (idx < 4) ? (t4*4 + idx) : (64 + t4*4 + idx - 4);
}

__global__ __launch_bounds__(256)
void chunk_stats() {
    const int c = blockIdx.x, bh = blockIdx.y;
    const int b = bh >> 3, h = bh & 7;
    const int base = b*TT + c*TCH;
    const int hoff = h*DKK;
    __shared__ float EKs[8*132];
    __shared__ float Vs[8*132];
    __shared__ float red[8*128];
    const int tid = threadIdx.x;
    const int tx = tid & 15, ty = tid >> 4;
    const int trow = tid >> 5;
    const int col = (tid & 31) << 2;
    float acc[8][8];
#pragma unroll
    for (int i = 0; i < 8; i++)
#pragma unroll
        for (int j = 0; j < 8; j++) acc[i][j] = 0.f;
    float ps0 = 0.f, ps1 = 0.f, ps2 = 0.f, ps3 = 0.f;

    for (int tt = 0; tt < TCH/8; tt++) {
        int row = base + tt*8 + trow;
        float4 kv = *(const float4*)(g_EK + (size_t)row*HIDN + hoff + col);
        kv.x = expf(kv.x); kv.y = expf(kv.y); kv.z = expf(kv.z); kv.w = expf(kv.w);
        *(float4*)(g_EK + (size_t)row*HIDN + hoff + col) = kv;
        ps0 += kv.x; ps1 += kv.y; ps2 += kv.z; ps3 += kv.w;
        *(float4*)&EKs[trow*132 + col] = kv;
        float4 vv = *(const float4*)(g_V + (size_t)row*HIDN + hoff + col);
        *(float4*)&Vs[trow*132 + col] = vv;
        __syncthreads();
#pragma unroll
        for (int k = 0; k < 8; k++) MICRO_FMA(EKs, Vs, k);
        __syncthreads();
    }
    red[trow*128 + col + 0] = ps0; red[trow*128 + col + 1] = ps1;
    red[trow*128 + col + 2] = ps2; red[trow*128 + col + 3] = ps3;
    __syncthreads();
    if (tid < DKK) {
        float s = 0.f;
#pragma unroll
        for (int r = 0; r < 8; r++) s += red[r*128 + tid];
        g_Asum[(bh*NCHUNK + c)*DKK + tid] = s;
    }
    size_t cb = ((size_t)(bh*NCHUNK + c))*DKK*DKK;
#pragma unroll
    for (int i = 0; i < 8; i++) {
        int dk = fragmap(i, ty);
        float4 s0 = make_float4(acc[i][0], acc[i][1], acc[i][2], acc[i][3]);
        float4 s1 = make_float4(acc[i][4], acc[i][5], acc[i][6], acc[i][7]);
        *(float4*)(g_Cc + cb + (size_t)dk*DKK + tx*4)      = s0;
        *(float4*)(g_Cc + cb + (size_t)dk*DKK + 64 + tx*4) = s1;
    }
}

__global__ void scan_asum() {
    int bh = blockIdx.x, dk = threadIdx.x;
    float run = 0.f;
    for (int c = 0; c < NCHUNK; c++) {
        int i = (bh*NCHUNK + c)*DKK + dk;
        float v = g_Asum[i]; g_Asum[i] = run; run += v;
    }
}
__global__ void scan_cc() {
    int bh = blockIdx.y;
    int idx = blockIdx.x*256 + threadIdx.x;
    float run = 0.f;
    for (int c = 0; c < NCHUNK; c++) {
        size_t p = ((size_t)(bh*NCHUNK + c))*(DKK*DKK) + idx;
        float v = g_Cc[p]; g_Cc[p] = run; run += v;
    }
}

__global__ void compute_qhat() {
    const int c = blockIdx.x, bh = blockIdx.y;
    const int b = bh >> 3, h = bh & 7;
    const int base = b*TT + c*TCH;
    const int dk = threadIdx.x;
    const float scale = 0.08838834764831845f;
    float run = g_Asum[(bh*NCHUNK + c)*DKK + dk];
    for (int t = 0; t < TCH; t++) {
        size_t gi = (size_t)(base + t)*HIDN + h*DKK + dk;
        run += g_EK[gi];
        g_QH[gi] = g_Q[gi] / run * scale;
    }
}

__global__ __launch_bounds__(256)
void chunk_out() {
    extern __shared__ float sm[];
    float* Ps  = sm;
    float* Asm = sm + 128*132;
    float* Bsm = Asm + 8*132;
    const int c = blockIdx.x, bh = blockIdx.y;
    const int b = bh >> 3, h = bh & 7;
    const int base = b*TT + c*TCH;
    const int hoff = h*DKK;
    const int tid = threadIdx.x;
    const int tx = tid & 15, ty = tid >> 4;
    const int lr = tid >> 1;
    const int lk = (tid & 1) << 2;
    const int trow = tid >> 5, col = (tid & 31) << 2;
    float acc[8][8];
#pragma unroll
    for (int i = 0; i < 8; i++)
#pragma unroll
        for (int j = 0; j < 8; j++) acc[i][j] = 0.f;

    for (int kt = 0; kt < DKK/8; kt++) {
        float4 va = *(const float4*)(g_QH + (size_t)(base+lr)*HIDN + hoff + kt*8 + lk);
        Asm[(lk+0)*132 + lr] = va.x; Asm[(lk+1)*132 + lr] = va.y;
        Asm[(lk+2)*132 + lr] = va.z; Asm[(lk+3)*132 + lr] = va.w;
        float4 vb = *(const float4*)(g_EK + (size_t)(base+lr)*HIDN + hoff + kt*8 + lk);
        Bsm[(lk+0)*132 + lr] = vb.x; Bsm[(lk+1)*132 + lr] = vb.y;
        Bsm[(lk+2)*132 + lr] = vb.z; Bsm[(lk+3)*132 + lr] = vb.w;
        __syncthreads();
#pragma unroll
        for (int k = 0; k < 8; k++) MICRO_FMA(Asm, Bsm, k);
        __syncthreads();
    }
#pragma unroll
    for (int i = 0; i < 8; i++) {
        int t = fragmap(i, ty);
#pragma unroll
        for (int j = 0; j < 8; j++) {
            int s = fragmap(j, tx);
            Ps[t*132 + s] = (s <= t) ? acc[i][j] : 0.f;
        }
    }
    __syncthreads();
#pragma unroll
    for (int i = 0; i < 8; i++)
#pragma unroll
        for (int j = 0; j < 8; j++) acc[i][j] = 0.f;

    for (int st = 0; st < TCH/8; st++) {
        float4 vv = *(const float4*)(g_V + (size_t)(base + st*8 + trow)*HIDN + hoff + col);
        *(float4*)&Bsm[trow*132 + col] = vv;
        __syncthreads();
#pragma unroll
        for (int k = 0; k < 8; k++) {
            int s = st*8 + k;
            float av[8];
#pragma unroll
            for (int i = 0; i < 4; i++) av[i]   = Ps[(ty*4 + i)*132 + s];
#pragma unroll
            for (int i = 0; i < 4; i++) av[4+i] = Ps[(64 + ty*4 + i)*132 + s];
            float4 b0 = *(const float4*)&Bsm[k*132 + tx*4];
            float4 b1 = *(const float4*)&Bsm[k*132 + 64 + tx*4];
            float bv[8] = {b0.x,b0.y,b0.z,b0.w,b1.x,b1.y,b1.z,b1.w};
#pragma unroll
            for (int i = 0; i < 8; i++)
#pragma unroll
                for (int j = 0; j < 8; j++) acc[i][j] += av[i]*bv[j];
        }
        __syncthreads();
    }

    size_t cb = ((size_t)(bh*NCHUNK + c))*DKK*DKK;
    for (int kt = 0; kt < DKK/8; kt++) {
        float4 va = *(const float4*)(g_QH + (size_t)(base+lr)*HIDN + hoff + kt*8 + lk);
        Asm[(lk+0)*132 + lr] = va.x; Asm[(lk+1)*132 + lr] = va.y;
        Asm[(lk+2)*132 + lr] = va.z; Asm[(lk+3)*132 + lr] = va.w;
        float4 vb = *(const float4*)(g_Cc + cb + (size_t)(kt*8 + trow)*DKK + col);
        *(float4*)&Bsm[trow*132 + col] = vb;
        __syncthreads();
#pragma unroll
        for (int k = 0; k < 8; k++) MICRO_FMA(Asm, Bsm, k);
        __syncthreads();
    }

#pragma unroll
    for (int i = 0; i < 8; i++) {
        int t = fragmap(i, ty);
        float4 s0 = make_float4(acc[i][0], acc[i][1], acc[i][2], acc[i][3]);
        float4 s1 = make_float4(acc[i][4], acc[i][5], acc[i][6], acc[i][7]);
        *(float4*)(g_O + (size_t)(base+t)*HIDN + hoff + tx*4)      = s0;
        *(float4*)(g_O + (size_t)(base+t)*HIDN + hoff + 64 + tx*4) = s1;
    }
}

__global__ __launch_bounds__(256)
void epilogue_k(const float* __restrict__ gnw) {
    __shared__ float red[256];
    const int n = blockIdx.x, tid = threadIdx.x;
    float4 ov = *((const float4*)(g_O + (size_t)n*HIDN) + tid);
    float ss = ov.x*ov.x + ov.y*ov.y + ov.z*ov.z + ov.w*ov.w;
    red[tid] = ss;
    __syncthreads();
    for (int s = 128; s > 0; s >>= 1) {
        if (tid < s) red[tid] += red[tid + s];
        __syncthreads();
    }
    float rms = rsqrtf(red[0] * (1.f/HIDN) + 1e-5f);
    float4 gv = *((const float4*)(g_gate + (size_t)n*HIDN) + tid);
    float4 wv = *((const float4*)gnw + tid);
    float4 u;
    u.x = ov.x*rms*wv.x * gv.x / (1.f + expf(-gv.x));
    u.y = ov.y*rms*wv.y * gv.y / (1.f + expf(-gv.y));
    u.z = ov.z*rms*wv.z * gv.z / (1.f + expf(-gv.z));
    u.w = ov.w*rms*wv.w * gv.w / (1.f + expf(-gv.w));
    *((float4*)(g_U + (size_t)n*HIDN) + tid) = u;
}

extern "C" void kernel_launch(void* const* d_in, const int* in_sizes, int n_in,
                              void* d_out, int out_size) {
    const float* x   = (const float*)d_in[0];
    const float* Wq  = (const float*)d_in[1];
    const float* Wk  = (const float*)d_in[2];
    const float* Wv  = (const float*)d_in[3];
    const float* Wg1 = (const float*)d_in[4];
    const float* Wg2 = (const float*)d_in[5];
    const float* gnw = (const float*)d_in[6];
    const float* Wo  = (const float*)d_in[7];
    float* out = (float*)d_out;

    float *Q, *EK, *V, *G1, *GATE, *U;
    cudaGetSymbolAddress((void**)&Q,    g_Q);
    cudaGetSymbolAddress((void**)&EK,   g_EK);
    cudaGetSymbolAddress((void**)&V,    g_V);
    cudaGetSymbolAddress((void**)&G1,   g_G1);
    cudaGetSymbolAddress((void**)&GATE, g_gate);
    cudaGetSymbolAddress((void**)&U,    g_U);

    const int CO_SMEM = (128*132 + 2*8*132) * 4;  // 76032 B
    cudaFuncSetAttribute(chunk_out, cudaFuncAttributeMaxDynamicSharedMemorySize, CO_SMEM);
    cudaFuncSetAttribute(gemm_mma<0>, cudaFuncAttributeMaxDynamicSharedMemorySize, GEMM_SMEM);
    cudaFuncSetAttribute(gemm_mma<1>, cudaFuncAttributeMaxDynamicSharedMemorySize, GEMM_SMEM);

    dim3 blk(256);
    gemm_mma<1><<<dim3(8,32), blk, GEMM_SMEM>>>(x, Wq, Q, NROWS, HIDN, HIDN);   // silu(x Wq^T)
    gemm_mma<0><<<dim3(8,32), blk, GEMM_SMEM>>>(x, Wk, EK, NROWS, HIDN, HIDN);
    gemm_mma<0><<<dim3(8,32), blk, GEMM_SMEM>>>(x, Wv, V, NROWS, HIDN, HIDN);
    gemm_mma<0><<<dim3(1,32), blk, GEMM_SMEM>>>(x, Wg1, G1, NROWS, 128, HIDN);
    gemm_mma<0><<<dim3(8,32), blk, GEMM_SMEM>>>(G1, Wg2, GATE, NROWS, HIDN, 128);
    chunk_stats<<<dim3(NCHUNK, NBH), blk>>>();
    scan_asum<<<NBH, DKK>>>();
    scan_cc<<<dim3(64, NBH), 256>>>();
    compute_qhat<<<dim3(NCHUNK, NBH), DKK>>>();
    chunk_out<<<dim3(NCHUNK, NBH), blk, CO_SMEM>>>();
    epilogue_k<<<NROWS, blk>>>(gnw);
    gemm_mma<0><<<dim3(8,32), blk, GEMM_SMEM>>>(U, Wo, out, NROWS, HIDN, HIDN);
}

// round 4
// speedup vs baseline: 2.0829x; 1.2059x over previous
#include <cuda_runtime.h>
#include <cuda_bf16.h>
#include <cstdint>
#include <math.h>

// Problem dims
#define BB 2
#define TT 2048
#define HIDN 1024
#define NH 8
#define DKK 128
#define NROWS (BB*TT)      // 4096
#define TCH 128
#define NCHUNK (TT/TCH)    // 16
#define NBH (BB*NH)        // 16

#define SMEM_SWZ(off) ((off) ^ (((off) >> 3) & 0x70))
typedef __nv_bfloat16 bf16;

// -------- fp32 scratch --------
__device__ float g_Q[NROWS*HIDN];
__device__ float g_EK[NROWS*HIDN];
__device__ float g_V[NROWS*HIDN];
__device__ float g_gate[NROWS*HIDN];
__device__ float g_QH[NROWS*HIDN];
__device__ float g_O[NROWS*HIDN];
__device__ float g_Asum[NBH*NCHUNK*DKK];
__device__ float g_Cc[NBH*NCHUNK*DKK*DKK];
// -------- split-bf16 scratch --------
__device__ bf16 g_xhi[NROWS*HIDN],  g_xlo[NROWS*HIDN];
__device__ bf16 g_Wqhi[HIDN*HIDN],  g_Wqlo[HIDN*HIDN];
__device__ bf16 g_Wkhi[HIDN*HIDN],  g_Wklo[HIDN*HIDN];
__device__ bf16 g_Wvhi[HIDN*HIDN],  g_Wvlo[HIDN*HIDN];
__device__ bf16 g_Wohi[HIDN*HIDN],  g_Wolo[HIDN*HIDN];
__device__ bf16 g_Wg1hi[128*HIDN],  g_Wg1lo[128*HIDN];
__device__ bf16 g_Wg2hi[HIDN*128],  g_Wg2lo[HIDN*128];
__device__ bf16 g_G1hi[NROWS*128],  g_G1lo[NROWS*128];
__device__ bf16 g_Uhi[NROWS*HIDN],  g_Ulo[NROWS*HIDN];

// ================= helpers =================
__device__ __forceinline__ uint32_t smem_u32(const void* p) {
    uint32_t a;
    asm("{ .reg .u64 t; cvta.to.shared.u64 t, %1; cvt.u32.u64 %0, t; }" : "=r"(a) : "l"(p));
    return a;
}
__device__ __forceinline__ void ldsm4(uint32_t* r, uint32_t addr) {
    asm volatile("ldmatrix.sync.aligned.m8n8.x4.shared.b16 {%0,%1,%2,%3}, [%4];"
        : "=r"(r[0]), "=r"(r[1]), "=r"(r[2]), "=r"(r[3]) : "r"(addr));
}
__device__ __forceinline__ void mma_bf16(float* d, const uint32_t* a, const uint32_t* b) {
    asm volatile("mma.sync.aligned.m16n8k16.row.col.f32.bf16.bf16.f32 "
        "{%0,%1,%2,%3}, {%4,%5,%6,%7}, {%8,%9}, {%0,%1,%2,%3};"
        : "+f"(d[0]), "+f"(d[1]), "+f"(d[2]), "+f"(d[3])
        : "r"(a[0]), "r"(a[1]), "r"(a[2]), "r"(a[3]), "r"(b[0]), "r"(b[1]));
}
#define CP_ASYNC16(dst, src) \
    asm volatile("cp.async.cg.shared.global [%0], [%1], 16;" :: "r"(dst), "l"(src) : "memory")
#define CP_COMMIT() asm volatile("cp.async.commit_group;" ::: "memory")
#define CP_WAIT2()  asm volatile("cp.async.wait_group 2;" ::: "memory")

// ================ split conversion (fp32 -> hi/lo bf16) ================
__global__ __launch_bounds__(256)
void convert_split(const float* __restrict__ src, bf16* __restrict__ hi,
                   bf16* __restrict__ lo, int n) {
    int i = (blockIdx.x * 256 + threadIdx.x) * 4;
    if (i >= n) return;
    float4 v = *(const float4*)(src + i);
    bf16 h0 = __float2bfloat16_rn(v.x), h1 = __float2bfloat16_rn(v.y);
    bf16 h2 = __float2bfloat16_rn(v.z), h3 = __float2bfloat16_rn(v.w);
    bf16 l0 = __float2bfloat16_rn(v.x - __bfloat162float(h0));
    bf16 l1 = __float2bfloat16_rn(v.y - __bfloat162float(h1));
    bf16 l2 = __float2bfloat16_rn(v.z - __bfloat162float(h2));
    bf16 l3 = __float2bfloat16_rn(v.w - __bfloat162float(h3));
    __nv_bfloat162 hp0 = __halves2bfloat162(h0, h1), hp1 = __halves2bfloat162(h2, h3);
    __nv_bfloat162 lp0 = __halves2bfloat162(l0, l1), lp1 = __halves2bfloat162(l2, l3);
    uint2 hu; hu.x = *(uint32_t*)&hp0; hu.y = *(uint32_t*)&hp1;
    uint2 lu; lu.x = *(uint32_t*)&lp0; lu.y = *(uint32_t*)&lp1;
    *(uint2*)(hi + i) = hu;
    *(uint2*)(lo + i) = lu;
}

// ============ cp.async tensor-core GEMM: C[M,N] = A[M,K] B[N,K]^T ============
#define TLA_HI 0
#define TLA_LO 16384
#define TLB_HI 32768
#define TLB_LO 49152
#define STG_STRIDE 65536
#define NSTAGE 3
#define GEMM_SMEM (NSTAGE*STG_STRIDE + 1024)

__device__ __forceinline__ void issue_stage(uint32_t sa,
        const bf16* __restrict__ Ahi, const bf16* __restrict__ Alo,
        const bf16* __restrict__ Bhi, const bf16* __restrict__ Blo,
        int rowA, int rowB, int K, int k0, int tid) {
#pragma unroll
    for (int t = 0; t < 16; t++) {
        const int tile = t >> 2;
        int idx = t * 256 + tid;
        int r = (idx >> 3) & 127;
        int c16 = idx & 7;
        const bf16* base = (tile == 0) ? Ahi : (tile == 1) ? Alo : (tile == 2) ? Bhi : Blo;
        int rowg = ((tile < 2) ? rowA : rowB) + r;
        const void* src = base + (size_t)rowg * K + k0 + c16 * 8;
        uint32_t dst = sa + tile * 16384 + SMEM_SWZ((uint32_t)(r * 128 + c16 * 16));
        CP_ASYNC16(dst, src);
    }
}

__device__ __forceinline__ void store_pair_split(bf16* Chi, bf16* Clo, size_t off,
                                                 float v0, float v1) {
    bf16 h0 = __float2bfloat16_rn(v0), h1 = __float2bfloat16_rn(v1);
    bf16 l0 = __float2bfloat16_rn(v0 - __bfloat162float(h0));
    bf16 l1 = __float2bfloat16_rn(v1 - __bfloat162float(h1));
    __nv_bfloat162 hp = __halves2bfloat162(h0, h1);
    __nv_bfloat162 lp = __halves2bfloat162(l0, l1);
    *(uint32_t*)(Chi + off) = *(uint32_t*)&hp;
    *(uint32_t*)(Clo + off) = *(uint32_t*)&lp;
}

__device__ __forceinline__ void gemm_core(
        const bf16* __restrict__ Ahi, const bf16* __restrict__ Alo,
        const bf16* __restrict__ Bhi, const bf16* __restrict__ Blo,
        float* __restrict__ C, bf16* __restrict__ Chi, bf16* __restrict__ Clo,
        int N, int K, int rowA, int rowB, int act, int outsplit) {
    extern __shared__ char dynsm[];
    char* tile = (char*)((((uintptr_t)dynsm) + 1023) & ~(uintptr_t)1023);
    const uint32_t sa0 = smem_u32(tile);
    const int tid = threadIdx.x;
    const int wid = tid >> 5, l = tid & 31;
    const int warp_m = wid >> 1, warp_n = wid & 1;

    float acc[2][8][4];
#pragma unroll
    for (int mf = 0; mf < 2; mf++)
#pragma unroll
        for (int nf = 0; nf < 8; nf++)
#pragma unroll
            for (int j = 0; j < 4; j++) acc[mf][nf][j] = 0.f;

    const int a_row = warp_m * 32 + (l & 15);
    const int a_kb  = (l >> 4) * 16;
    const int b_row = warp_n * 64 + (l & 7) + ((l >> 4) & 1) * 8;
    const int b_kb  = ((l >> 3) & 1) * 16;

    const int nk = K >> 6;
#pragma unroll
    for (int s = 0; s < NSTAGE; s++) {
        if (s < nk) issue_stage(sa0 + s * STG_STRIDE, Ahi, Alo, Bhi, Blo, rowA, rowB, K, s << 6, tid);
        CP_COMMIT();
    }
    int sidx = 0;
    for (int kb = 0; kb < nk; kb++) {
        CP_WAIT2();
        __syncthreads();
        const uint32_t st = sa0 + sidx * STG_STRIDE;
#pragma unroll
        for (int ks = 0; ks < 4; ks++) {
            const int koff = ks * 32;
            uint32_t Ah[2][4], Al[2][4], Bh[4][4], Bl[4][4];
#pragma unroll
            for (int mf = 0; mf < 2; mf++) {
                uint32_t ro = SMEM_SWZ((uint32_t)((a_row + mf * 16) * 128 + koff + a_kb));
                ldsm4(Ah[mf], st + TLA_HI + ro);
                ldsm4(Al[mf], st + TLA_LO + ro);
            }
#pragma unroll
            for (int nf2 = 0; nf2 < 4; nf2++) {
                uint32_t ro = SMEM_SWZ((uint32_t)((b_row + nf2 * 16) * 128 + koff + b_kb));
                ldsm4(Bh[nf2], st + TLB_HI + ro);
                ldsm4(Bl[nf2], st + TLB_LO + ro);
            }
#pragma unroll
            for (int mf = 0; mf < 2; mf++)
#pragma unroll
                for (int nf = 0; nf < 8; nf++) {
                    const int nf2 = nf >> 1, ho = (nf & 1) * 2;
                    mma_bf16(acc[mf][nf], Ah[mf], &Bh[nf2][ho]);
                    mma_bf16(acc[mf][nf], Ah[mf], &Bl[nf2][ho]);
                    mma_bf16(acc[mf][nf], Al[mf], &Bh[nf2][ho]);
                }
        }
        __syncthreads();
        if (kb + NSTAGE < nk)
            issue_stage(sa0 + sidx * STG_STRIDE, Ahi, Alo, Bhi, Blo, rowA, rowB, K, (kb + NSTAGE) << 6, tid);
        CP_COMMIT();
        sidx = (sidx + 1 == NSTAGE) ? 0 : sidx + 1;
    }

#pragma unroll
    for (int mf = 0; mf < 2; mf++)
#pragma unroll
        for (int nf = 0; nf < 8; nf++) {
            int r0 = rowA + warp_m * 32 + mf * 16 + (l >> 2);
            int cc = rowB + warp_n * 64 + nf * 8 + (l & 3) * 2;
            float v0 = acc[mf][nf][0], v1 = acc[mf][nf][1];
            float v2 = acc[mf][nf][2], v3 = acc[mf][nf][3];
            if (act) {
                v0 = v0 / (1.f + expf(-v0));
                v1 = v1 / (1.f + expf(-v1));
                v2 = v2 / (1.f + expf(-v2));
                v3 = v3 / (1.f + expf(-v3));
            }
            if (!outsplit) {
                *(float2*)(C + (size_t)r0 * N + cc)       = make_float2(v0, v1);
                *(float2*)(C + (size_t)(r0 + 8) * N + cc) = make_float2(v2, v3);
            } else {
                store_pair_split(Chi, Clo, (size_t)r0 * N + cc, v0, v1);
                store_pair_split(Chi, Clo, (size_t)(r0 + 8) * N + cc, v2, v3);
            }
        }
}

template<int ACT, int OSPLIT>
__global__ __launch_bounds__(256, 1)
void gemm_bf16(const bf16* Ahi, const bf16* Alo, const bf16* Bhi, const bf16* Blo,
               float* C, bf16* Chi, bf16* Clo, int N, int K) {
    gemm_core(Ahi, Alo, Bhi, Blo, C, Chi, Clo, N, K,
              blockIdx.y * 128, blockIdx.x * 128, ACT, OSPLIT);
}

// fused Q/K/V projection: grid (24, 32); which = bx>>3
__global__ __launch_bounds__(256, 1)
void gemm_qkv() {
    const int which = blockIdx.x >> 3;
    const int colb = blockIdx.x & 7;
    const bf16 *Bh, *Bl;
    float* C;
    if (which == 0)      { Bh = g_Wqhi; Bl = g_Wqlo; C = g_Q; }
    else if (which == 1) { Bh = g_Wkhi; Bl = g_Wklo; C = g_EK; }
    else                 { Bh = g_Wvhi; Bl = g_Wvlo; C = g_V; }
    gemm_core(g_xhi, g_xlo, Bh, Bl, C, nullptr, nullptr, HIDN, HIDN,
              blockIdx.y * 128, colb * 128, which == 0, 0);
}

// ================= attention kernels (SIMT fp32) ==================
#define MICRO_FMA(Aptr, Bptr, kk) do {                                    \
    float4 a0 = *(const float4*)&(Aptr)[(kk)*132 + ty*4];                 \
    float4 a1 = *(const float4*)&(Aptr)[(kk)*132 + 64 + ty*4];            \
    float4 b0 = *(const float4*)&(Bptr)[(kk)*132 + tx*4];                 \
    float4 b1 = *(const float4*)&(Bptr)[(kk)*132 + 64 + tx*4];            \
    float av[8] = {a0.x,a0.y,a0.z,a0.w,a1.x,a1.y,a1.z,a1.w};              \
    float bv[8] = {b0.x,b0.y,b0.z,b0.w,b1.x,b1.y,b1.z,b1.w};              \
    _Pragma("unroll") for (int ii=0; ii<8; ii++)                          \
      _Pragma("unroll") for (int jj=0; jj<8; jj++)                        \
        acc[ii][jj] += av[ii]*bv[jj];                                     \
} while(0)

__device__ __forceinline__ int fragmap(int idx, int t4) {
    return (idx < 4) ? (t4*4 + idx) : (64 + t4*4 + idx - 4);
}

__global__ __launch_bounds__(256)
void chunk_stats() {
    const int c = blockIdx.x, bh = blockIdx.y;
    const int b = bh >> 3, h = bh & 7;
    const int base = b*TT + c*TCH;
    const int hoff = h*DKK;
    __shared__ float EKs[8*132];
    __shared__ float Vs[8*132];
    __shared__ float red[8*128];
    const int tid = threadIdx.x;
    const int tx = tid & 15, ty = tid >> 4;
    const int trow = tid >> 5;
    const int col = (tid & 31) << 2;
    float acc[8][8];
#pragma unroll
    for (int i = 0; i < 8; i++)
#pragma unroll
        for (int j = 0; j < 8; j++) acc[i][j] = 0.f;
    float ps0 = 0.f, ps1 = 0.f, ps2 = 0.f, ps3 = 0.f;

    for (int tt = 0; tt < TCH/8; tt++) {
        int row = base + tt*8 + trow;
        float4 kv = *(const float4*)(g_EK + (size_t)row*HIDN + hoff + col);
        kv.x = expf(kv.x); kv.y = expf(kv.y); kv.z = expf(kv.z); kv.w = expf(kv.w);
        *(float4*)(g_EK + (size_t)row*HIDN + hoff + col) = kv;
        ps0 += kv.x; ps1 += kv.y; ps2 += kv.z; ps3 += kv.w;
        *(float4*)&EKs[trow*132 + col] = kv;
        float4 vv = *(const float4*)(g_V + (size_t)row*HIDN + hoff + col);
        *(float4*)&Vs[trow*132 + col] = vv;
        __syncthreads();
#pragma unroll
        for (int k = 0; k < 8; k++) MICRO_FMA(EKs, Vs, k);
        __syncthreads();
    }
    red[trow*128 + col + 0] = ps0; red[trow*128 + col + 1] = ps1;
    red[trow*128 + col + 2] = ps2; red[trow*128 + col + 3] = ps3;
    __syncthreads();
    if (tid < DKK) {
        float s = 0.f;
#pragma unroll
        for (int r = 0; r < 8; r++) s += red[r*128 + tid];
        g_Asum[(bh*NCHUNK + c)*DKK + tid] = s;
    }
    size_t cb = ((size_t)(bh*NCHUNK + c))*DKK*DKK;
#pragma unroll
    for (int i = 0; i < 8; i++) {
        int dk = fragmap(i, ty);
        float4 s0 = make_float4(acc[i][0], acc[i][1], acc[i][2], acc[i][3]);
        float4 s1 = make_float4(acc[i][4], acc[i][5], acc[i][6], acc[i][7]);
        *(float4*)(g_Cc + cb + (size_t)dk*DKK + tx*4)      = s0;
        *(float4*)(g_Cc + cb + (size_t)dk*DKK + 64 + tx*4) = s1;
    }
}

__global__ void scan_asum() {
    int bh = blockIdx.x, dk = threadIdx.x;
    float run = 0.f;
    for (int c = 0; c < NCHUNK; c++) {
        int i = (bh*NCHUNK + c)*DKK + dk;
        float v = g_Asum[i]; g_Asum[i] = run; run += v;
    }
}
__global__ void scan_cc() {
    int bh = blockIdx.y;
    int idx = blockIdx.x*256 + threadIdx.x;
    float run = 0.f;
    for (int c = 0; c < NCHUNK; c++) {
        size_t p = ((size_t)(bh*NCHUNK + c))*(DKK*DKK) + idx;
        float v = g_Cc[p]; g_Cc[p] = run; run += v;
    }
}

__global__ void compute_qhat() {
    const int c = blockIdx.x, bh = blockIdx.y;
    const int b = bh >> 3, h = bh & 7;
    const int base = b*TT + c*TCH;
    const int dk = threadIdx.x;
    const float scale = 0.08838834764831845f;
    float run = g_Asum[(bh*NCHUNK + c)*DKK + dk];
    for (int t = 0; t < TCH; t++) {
        size_t gi = (size_t)(base + t)*HIDN + h*DKK + dk;
        run += g_EK[gi];
        g_QH[gi] = g_Q[gi] / run * scale;
    }
}

__global__ __launch_bounds__(256)
void chunk_out() {
    extern __shared__ float sm[];
    float* Ps  = sm;
    float* Asm = sm + 128*132;
    float* Bsm = Asm + 8*132;
    const int c = blockIdx.x, bh = blockIdx.y;
    const int b = bh >> 3, h = bh & 7;
    const int base = b*TT + c*TCH;
    const int hoff = h*DKK;
    const int tid = threadIdx.x;
    const int tx = tid & 15, ty = tid >> 4;
    const int lr = tid >> 1;
    const int lk = (tid & 1) << 2;
    const int trow = tid >> 5, col = (tid & 31) << 2;
    float acc[8][8];
#pragma unroll
    for (int i = 0; i < 8; i++)
#pragma unroll
        for (int j = 0; j < 8; j++) acc[i][j] = 0.f;

    for (int kt = 0; kt < DKK/8; kt++) {
        float4 va = *(const float4*)(g_QH + (size_t)(base+lr)*HIDN + hoff + kt*8 + lk);
        Asm[(lk+0)*132 + lr] = va.x; Asm[(lk+1)*132 + lr] = va.y;
        Asm[(lk+2)*132 + lr] = va.z; Asm[(lk+3)*132 + lr] = va.w;
        float4 vb = *(const float4*)(g_EK + (size_t)(base+lr)*HIDN + hoff + kt*8 + lk);
        Bsm[(lk+0)*132 + lr] = vb.x; Bsm[(lk+1)*132 + lr] = vb.y;
        Bsm[(lk+2)*132 + lr] = vb.z; Bsm[(lk+3)*132 + lr] = vb.w;
        __syncthreads();
#pragma unroll
        for (int k = 0; k < 8; k++) MICRO_FMA(Asm, Bsm, k);
        __syncthreads();
    }
#pragma unroll
    for (int i = 0; i < 8; i++) {
        int t = fragmap(i, ty);
#pragma unroll
        for (int j = 0; j < 8; j++) {
            int s = fragmap(j, tx);
            Ps[t*132 + s] = (s <= t) ? acc[i][j] : 0.f;
        }
    }
    __syncthreads();
#pragma unroll
    for (int i = 0; i < 8; i++)
#pragma unroll
        for (int j = 0; j < 8; j++) acc[i][j] = 0.f;

    for (int st = 0; st < TCH/8; st++) {
        float4 vv = *(const float4*)(g_V + (size_t)(base + st*8 + trow)*HIDN + hoff + col);
        *(float4*)&Bsm[trow*132 + col] = vv;
        __syncthreads();
#pragma unroll
        for (int k = 0; k < 8; k++) {
            int s = st*8 + k;
            float av[8];
#pragma unroll
            for (int i = 0; i < 4; i++) av[i]   = Ps[(ty*4 + i)*132 + s];
#pragma unroll
            for (int i = 0; i < 4; i++) av[4+i] = Ps[(64 + ty*4 + i)*132 + s];
            float4 b0 = *(const float4*)&Bsm[k*132 + tx*4];
            float4 b1 = *(const float4*)&Bsm[k*132 + 64 + tx*4];
            float bv[8] = {b0.x,b0.y,b0.z,b0.w,b1.x,b1.y,b1.z,b1.w};
#pragma unroll
            for (int i = 0; i < 8; i++)
#pragma unroll
                for (int j = 0; j < 8; j++) acc[i][j] += av[i]*bv[j];
        }
        __syncthreads();
    }

    size_t cb = ((size_t)(bh*NCHUNK + c))*DKK*DKK;
    for (int kt = 0; kt < DKK/8; kt++) {
        float4 va = *(const float4*)(g_QH + (size_t)(base+lr)*HIDN + hoff + kt*8 + lk);
        Asm[(lk+0)*132 + lr] = va.x; Asm[(lk+1)*132 + lr] = va.y;
        Asm[(lk+2)*132 + lr] = va.z; Asm[(lk+3)*132 + lr] = va.w;
        float4 vb = *(const float4*)(g_Cc + cb + (size_t)(kt*8 + trow)*DKK + col);
        *(float4*)&Bsm[trow*132 + col] = vb;
        __syncthreads();
#pragma unroll
        for (int k = 0; k < 8; k++) MICRO_FMA(Asm, Bsm, k);
        __syncthreads();
    }

#pragma unroll
    for (int i = 0; i < 8; i++) {
        int t = fragmap(i, ty);
        float4 s0 = make_float4(acc[i][0], acc[i][1], acc[i][2], acc[i][3]);
        float4 s1 = make_float4(acc[i][4], acc[i][5], acc[i][6], acc[i][7]);
        *(float4*)(g_O + (size_t)(base+t)*HIDN + hoff + tx*4)      = s0;
        *(float4*)(g_O + (size_t)(base+t)*HIDN + hoff + 64 + tx*4) = s1;
    }
}

// epilogue: RMSNorm(o) * w * gate * sigmoid(gate) -> split bf16 U
__global__ __launch_bounds__(256)
void epilogue_k(const float* __restrict__ gnw) {
    __shared__ float red[256];
    const int n = blockIdx.x, tid = threadIdx.x;
    float4 ov = *((const float4*)(g_O + (size_t)n*HIDN) + tid);
    float ss = ov.x*ov.x + ov.y*ov.y + ov.z*ov.z + ov.w*ov.w;
    red[tid] = ss;
    __syncthreads();
    for (int s = 128; s > 0; s >>= 1) {
        if (tid < s) red[tid] += red[tid + s];
        __syncthreads();
    }
    float rms = rsqrtf(red[0] * (1.f/HIDN) + 1e-5f);
    float4 gv = *((const float4*)(g_gate + (size_t)n*HIDN) + tid);
    float4 wv = *((const float4*)gnw + tid);
    float4 u;
    u.x = ov.x*rms*wv.x * gv.x / (1.f + expf(-gv.x));
    u.y = ov.y*rms*wv.y * gv.y / (1.f + expf(-gv.y));
    u.z = ov.z*rms*wv.z * gv.z / (1.f + expf(-gv.z));
    u.w = ov.w*rms*wv.w * gv.w / (1.f + expf(-gv.w));
    size_t off = (size_t)n*HIDN + tid*4;
    store_pair_split(g_Uhi, g_Ulo, off, u.x, u.y);
    store_pair_split(g_Uhi, g_Ulo, off + 2, u.z, u.w);
}

extern "C" void kernel_launch(void* const* d_in, const int* in_sizes, int n_in,
                              void* d_out, int out_size) {
    const float* x   = (const float*)d_in[0];
    const float* Wq  = (const float*)d_in[1];
    const float* Wk  = (const float*)d_in[2];
    const float* Wv  = (const float*)d_in[3];
    const float* Wg1 = (const float*)d_in[4];
    const float* Wg2 = (const float*)d_in[5];
    const float* gnw = (const float*)d_in[6];
    const float* Wo  = (const float*)d_in[7];
    float* out = (float*)d_out;

    bf16 *xhi,*xlo,*wqh,*wql,*wkh,*wkl,*wvh,*wvl,*woh,*wol,*w1h,*w1l,*w2h,*w2l,*g1h,*g1l,*uh,*ul;
    float* gate;
    cudaGetSymbolAddress((void**)&xhi, g_xhi);  cudaGetSymbolAddress((void**)&xlo, g_xlo);
    cudaGetSymbolAddress((void**)&wqh, g_Wqhi); cudaGetSymbolAddress((void**)&wql, g_Wqlo);
    cudaGetSymbolAddress((void**)&wkh, g_Wkhi); cudaGetSymbolAddress((void**)&wkl, g_Wklo);
    cudaGetSymbolAddress((void**)&wvh, g_Wvhi); cudaGetSymbolAddress((void**)&wvl, g_Wvlo);
    cudaGetSymbolAddress((void**)&woh, g_Wohi); cudaGetSymbolAddress((void**)&wol, g_Wolo);
    cudaGetSymbolAddress((void**)&w1h, g_Wg1hi); cudaGetSymbolAddress((void**)&w1l, g_Wg1lo);
    cudaGetSymbolAddress((void**)&w2h, g_Wg2hi); cudaGetSymbolAddress((void**)&w2l, g_Wg2lo);
    cudaGetSymbolAddress((void**)&g1h, g_G1hi); cudaGetSymbolAddress((void**)&g1l, g_G1lo);
    cudaGetSymbolAddress((void**)&uh, g_Uhi);   cudaGetSymbolAddress((void**)&ul, g_Ulo);
    cudaGetSymbolAddress((void**)&gate, g_gate);

    const int CO_SMEM = (128*132 + 2*8*132) * 4;
    cudaFuncSetAttribute(chunk_out, cudaFuncAttributeMaxDynamicSharedMemorySize, CO_SMEM);
    cudaFuncSetAttribute(gemm_qkv, cudaFuncAttributeMaxDynamicSharedMemorySize, GEMM_SMEM);
    cudaFuncSetAttribute(gemm_bf16<0,0>, cudaFuncAttributeMaxDynamicSharedMemorySize, GEMM_SMEM);
    cudaFuncSetAttribute(gemm_bf16<0,1>, cudaFuncAttributeMaxDynamicSharedMemorySize, GEMM_SMEM);

    dim3 blk(256);
    // split conversions
    convert_split<<<NROWS*HIDN/1024, blk>>>(x, xhi, xlo, NROWS*HIDN);
    convert_split<<<HIDN*HIDN/1024, blk>>>(Wq, wqh, wql, HIDN*HIDN);
    convert_split<<<HIDN*HIDN/1024, blk>>>(Wk, wkh, wkl, HIDN*HIDN);
    convert_split<<<HIDN*HIDN/1024, blk>>>(Wv, wvh, wvl, HIDN*HIDN);
    convert_split<<<HIDN*HIDN/1024, blk>>>(Wo, woh, wol, HIDN*HIDN);
    convert_split<<<128*HIDN/1024, blk>>>(Wg1, w1h, w1l, 128*HIDN);
    convert_split<<<HIDN*128/1024, blk>>>(Wg2, w2h, w2l, HIDN*128);
    // projections
    gemm_qkv<<<dim3(24,32), blk, GEMM_SMEM>>>();
    gemm_bf16<0,1><<<dim3(1,32), blk, GEMM_SMEM>>>(xhi, xlo, w1h, w1l, nullptr, g1h, g1l, 128, HIDN);
    gemm_bf16<0,0><<<dim3(8,32), blk, GEMM_SMEM>>>(g1h, g1l, w2h, w2l, gate, nullptr, nullptr, HIDN, 128);
    // attention
    chunk_stats<<<dim3(NCHUNK, NBH), blk>>>();
    scan_asum<<<NBH, DKK>>>();
    scan_cc<<<dim3(64, NBH), 256>>>();
    compute_qhat<<<dim3(NCHUNK, NBH), DKK>>>();
    chunk_out<<<dim3(NCHUNK, NBH), blk, CO_SMEM>>>();
    epilogue_k<<<NROWS, blk>>>(gnw);
    // output projection
    gemm_bf16<0,0><<<dim3(8,32), blk, GEMM_SMEM>>>(uh, ul, woh, wol, out, nullptr, nullptr, HIDN, HIDN);
}

// round 5
// speedup vs baseline: 2.2874x; 1.0982x over previous
#include <cuda_runtime.h>
#include <cuda_bf16.h>
#include <cstdint>
#include <math.h>

// Problem dims
#define BB 2
#define TT 2048
#define HIDN 1024
#define NH 8
#define DKK 128
#define NROWS (BB*TT)      // 4096
#define TCH 128
#define NCHUNK (TT/TCH)    // 16
#define NBH (BB*NH)        // 16

#define SMEM_SWZ(off) ((off) ^ (((off) >> 3) & 0x70))
typedef __nv_bfloat16 bf16;

// -------- fp32 scratch --------
__device__ float g_Q[NROWS*HIDN];
__device__ float g_EK[NROWS*HIDN];     // raw k, then exp(k) in place
__device__ float g_V[NROWS*HIDN];
__device__ float g_gate[NROWS*HIDN];
__device__ float g_O[NROWS*HIDN];
__device__ float g_Asum[NBH*NCHUNK*DKK];
__device__ float g_CcT[NBH*NCHUNK*DKK*DKK];   // per-chunk (V^T EK) = Cc^T [dv][dk]
// -------- split-bf16 scratch --------
__device__ bf16 g_xhi[NROWS*HIDN],  g_xlo[NROWS*HIDN];
__device__ bf16 g_Wqhi[HIDN*HIDN],  g_Wqlo[HIDN*HIDN];
__device__ bf16 g_Wkhi[HIDN*HIDN],  g_Wklo[HIDN*HIDN];
__device__ bf16 g_Wvhi[HIDN*HIDN],  g_Wvlo[HIDN*HIDN];
__device__ bf16 g_Wohi[HIDN*HIDN],  g_Wolo[HIDN*HIDN];
__device__ bf16 g_Wg1hi[128*HIDN],  g_Wg1lo[128*HIDN];
__device__ bf16 g_Wg2hi[HIDN*128],  g_Wg2lo[HIDN*128];
__device__ bf16 g_G1hi[NROWS*128],  g_G1lo[NROWS*128];
__device__ bf16 g_Uhi[NROWS*HIDN],  g_Ulo[NROWS*HIDN];
__device__ bf16 g_EKhi[NROWS*HIDN], g_EKlo[NROWS*HIDN];   // exp(k), natural [t, dk]
__device__ bf16 g_QHhi[NROWS*HIDN], g_QHlo[NROWS*HIDN];   // qhat, natural [t, dk]
__device__ bf16 g_VThi[NBH*DKK*TT], g_VTlo[NBH*DKK*TT];   // [bh][dv][t]
__device__ bf16 g_CcThi[NBH*NCHUNK*DKK*DKK], g_CcTlo[NBH*NCHUNK*DKK*DKK]; // excl prefix

// ================= helpers =================
__device__ __forceinline__ uint32_t smem_u32(const void* p) {
    uint32_t a;
    asm("{ .reg .u64 t; cvta.to.shared.u64 t, %1; cvt.u32.u64 %0, t; }" : "=r"(a) : "l"(p));
    return a;
}
__device__ __forceinline__ void ldsm4(uint32_t* r, uint32_t addr) {
    asm volatile("ldmatrix.sync.aligned.m8n8.x4.shared.b16 {%0,%1,%2,%3}, [%4];"
        : "=r"(r[0]), "=r"(r[1]), "=r"(r[2]), "=r"(r[3]) : "r"(addr));
}
__device__ __forceinline__ void mma_bf16(float* d, const uint32_t* a, const uint32_t* b) {
    asm volatile("mma.sync.aligned.m16n8k16.row.col.f32.bf16.bf16.f32 "
        "{%0,%1,%2,%3}, {%4,%5,%6,%7}, {%8,%9}, {%0,%1,%2,%3};"
        : "+f"(d[0]), "+f"(d[1]), "+f"(d[2]), "+f"(d[3])
        : "r"(a[0]), "r"(a[1]), "r"(a[2]), "r"(a[3]), "r"(b[0]), "r"(b[1]));
}
#define CP_ASYNC16(dst, src) \
    asm volatile("cp.async.cg.shared.global [%0], [%1], 16;" :: "r"(dst), "l"(src) : "memory")
#define CP_COMMIT() asm volatile("cp.async.commit_group;" ::: "memory")
#define CP_WAIT2()  asm volatile("cp.async.wait_group 2;" ::: "memory")
#define CP_WAIT0()  asm volatile("cp.async.wait_group 0;" ::: "memory")

__device__ __forceinline__ void split2(float v0, float v1, uint32_t& h, uint32_t& lo) {
    bf16 h0 = __float2bfloat16_rn(v0), h1 = __float2bfloat16_rn(v1);
    bf16 l0 = __float2bfloat16_rn(v0 - __bfloat162float(h0));
    bf16 l1 = __float2bfloat16_rn(v1 - __bfloat162float(h1));
    __nv_bfloat162 hp = __halves2bfloat162(h0, h1);
    __nv_bfloat162 lp = __halves2bfloat162(l0, l1);
    h = *(uint32_t*)&hp; lo = *(uint32_t*)&lp;
}
__device__ __forceinline__ void store_pair_split(bf16* Chi, bf16* Clo, size_t off,
                                                 float v0, float v1) {
    uint32_t h, lo; split2(v0, v1, h, lo);
    *(uint32_t*)(Chi + off) = h;
    *(uint32_t*)(Clo + off) = lo;
}

// shared 64-K-wide 3-term MMA block (validated fragment mappings)
__device__ __forceinline__ void mma_block64(float acc[2][8][4],
        uint32_t sAhi, uint32_t sAlo, uint32_t sBhi, uint32_t sBlo,
        int a_row, int a_kb, int b_row, int b_kb) {
#pragma unroll
    for (int ks = 0; ks < 4; ks++) {
        const int koff = ks * 32;
        uint32_t Ah[2][4], Al[2][4], Bh[4][4], Bl[4][4];
#pragma unroll
        for (int mf = 0; mf < 2; mf++) {
            uint32_t ro = SMEM_SWZ((uint32_t)((a_row + mf * 16) * 128 + koff + a_kb));
            ldsm4(Ah[mf], sAhi + ro);
            ldsm4(Al[mf], sAlo + ro);
        }
#pragma unroll
        for (int nf2 = 0; nf2 < 4; nf2++) {
            uint32_t ro = SMEM_SWZ((uint32_t)((b_row + nf2 * 16) * 128 + koff + b_kb));
            ldsm4(Bh[nf2], sBhi + ro);
            ldsm4(Bl[nf2], sBlo + ro);
        }
#pragma unroll
        for (int mf = 0; mf < 2; mf++)
#pragma unroll
            for (int nf = 0; nf < 8; nf++) {
                const int nf2 = nf >> 1, ho = (nf & 1) * 2;
                mma_bf16(acc[mf][nf], Ah[mf], &Bh[nf2][ho]);
                mma_bf16(acc[mf][nf], Ah[mf], &Bl[nf2][ho]);
                mma_bf16(acc[mf][nf], Al[mf], &Bh[nf2][ho]);
            }
    }
}

// ================ split conversion (fp32 -> hi/lo bf16) ================
__global__ __launch_bounds__(256)
void convert_split(const float* __restrict__ src, bf16* __restrict__ hi,
                   bf16* __restrict__ lo, int n) {
    int i = (blockIdx.x * 256 + threadIdx.x) * 4;
    if (i >= n) return;
    float4 v = *(const float4*)(src + i);
    uint32_t h0, l0, h1, l1;
    split2(v.x, v.y, h0, l0);
    split2(v.z, v.w, h1, l1);
    uint2 hu; hu.x = h0; hu.y = h1;
    uint2 lu; lu.x = l0; lu.y = l1;
    *(uint2*)(hi + i) = hu;
    *(uint2*)(lo + i) = lu;
}

// ============ cp.async tensor-core GEMM: C[M,N] = A[M,K] B[N,K]^T ============
#define TLA_HI 0
#define TLA_LO 16384
#define TLB_HI 32768
#define TLB_LO 49152
#define STG_STRIDE 65536
#define NSTAGE 3
#define GEMM_SMEM (NSTAGE*STG_STRIDE + 1024)

__device__ __forceinline__ void issue_stage(uint32_t sa,
        const bf16* __restrict__ Ahi, const bf16* __restrict__ Alo,
        const bf16* __restrict__ Bhi, const bf16* __restrict__ Blo,
        int rowA, int rowB, int K, int k0, int tid) {
#pragma unroll
    for (int t = 0; t < 16; t++) {
        const int tile = t >> 2;
        int idx = t * 256 + tid;
        int r = (idx >> 3) & 127;
        int c16 = idx & 7;
        const bf16* base = (tile == 0) ? Ahi : (tile == 1) ? Alo : (tile == 2) ? Bhi : Blo;
        int rowg = ((tile < 2) ? rowA : rowB) + r;
        const void* src = base + (size_t)rowg * K + k0 + c16 * 8;
        uint32_t dst = sa + tile * 16384 + SMEM_SWZ((uint32_t)(r * 128 + c16 * 16));
        CP_ASYNC16(dst, src);
    }
}

__device__ __forceinline__ void gemm_core(
        const bf16* __restrict__ Ahi, const bf16* __restrict__ Alo,
        const bf16* __restrict__ Bhi, const bf16* __restrict__ Blo,
        float* __restrict__ C, bf16* __restrict__ Chi, bf16* __restrict__ Clo,
        int N, int K, int rowA, int rowB, int act, int outsplit) {
    extern __shared__ char dynsm[];
    char* tile = (char*)((((uintptr_t)dynsm) + 1023) & ~(uintptr_t)1023);
    const uint32_t sa0 = smem_u32(tile);
    const int tid = threadIdx.x;
    const int wid = tid >> 5, l = tid & 31;
    const int warp_m = wid >> 1, warp_n = wid & 1;

    float acc[2][8][4];
#pragma unroll
    for (int mf = 0; mf < 2; mf++)
#pragma unroll
        for (int nf = 0; nf < 8; nf++)
#pragma unroll
            for (int j = 0; j < 4; j++) acc[mf][nf][j] = 0.f;

    const int a_row = warp_m * 32 + (l & 15);
    const int a_kb  = (l >> 4) * 16;
    const int b_row = warp_n * 64 + (l & 7) + ((l >> 4) & 1) * 8;
    const int b_kb  = ((l >> 3) & 1) * 16;

    const int nk = K >> 6;
#pragma unroll
    for (int s = 0; s < NSTAGE; s++) {
        if (s < nk) issue_stage(sa0 + s * STG_STRIDE, Ahi, Alo, Bhi, Blo, rowA, rowB, K, s << 6, tid);
        CP_COMMIT();
    }
    int sidx = 0;
    for (int kb = 0; kb < nk; kb++) {
        CP_WAIT2();
        __syncthreads();
        const uint32_t st = sa0 + sidx * STG_STRIDE;
        mma_block64(acc, st + TLA_HI, st + TLA_LO, st + TLB_HI, st + TLB_LO,
                    a_row, a_kb, b_row, b_kb);
        __syncthreads();
        if (kb + NSTAGE < nk)
            issue_stage(sa0 + sidx * STG_STRIDE, Ahi, Alo, Bhi, Blo, rowA, rowB, K, (kb + NSTAGE) << 6, tid);
        CP_COMMIT();
        sidx = (sidx + 1 == NSTAGE) ? 0 : sidx + 1;
    }

#pragma unroll
    for (int mf = 0; mf < 2; mf++)
#pragma unroll
        for (int nf = 0; nf < 8; nf++) {
            int r0 = rowA + warp_m * 32 + mf * 16 + (l >> 2);
            int cc = rowB + warp_n * 64 + nf * 8 + (l & 3) * 2;
            float v0 = acc[mf][nf][0], v1 = acc[mf][nf][1];
            float v2 = acc[mf][nf][2], v3 = acc[mf][nf][3];
            if (act) {
                v0 = v0 / (1.f + expf(-v0));
                v1 = v1 / (1.f + expf(-v1));
                v2 = v2 / (1.f + expf(-v2));
                v3 = v3 / (1.f + expf(-v3));
            }
            if (!outsplit) {
                *(float2*)(C + (size_t)r0 * N + cc)       = make_float2(v0, v1);
                *(float2*)(C + (size_t)(r0 + 8) * N + cc) = make_float2(v2, v3);
            } else {
                store_pair_split(Chi, Clo, (size_t)r0 * N + cc, v0, v1);
                store_pair_split(Chi, Clo, (size_t)(r0 + 8) * N + cc, v2, v3);
            }
        }
}

template<int ACT, int OSPLIT>
__global__ __launch_bounds__(256, 1)
void gemm_bf16(const bf16* Ahi, const bf16* Alo, const bf16* Bhi, const bf16* Blo,
               float* C, bf16* Chi, bf16* Clo, int N, int K) {
    gemm_core(Ahi, Alo, Bhi, Blo, C, Chi, Clo, N, K,
              blockIdx.y * 128, blockIdx.x * 128, ACT, OSPLIT);
}

// fused Q/K/V projection: grid (24, 32); which = bx>>3
__global__ __launch_bounds__(256, 1)
void gemm_qkv() {
    const int which = blockIdx.x >> 3;
    const int colb = blockIdx.x & 7;
    const bf16 *Bh, *Bl;
    float* C;
    if (which == 0)      { Bh = g_Wqhi; Bl = g_Wqlo; C = g_Q; }
    else if (which == 1) { Bh = g_Wkhi; Bl = g_Wklo; C = g_EK; }
    else                 { Bh = g_Wvhi; Bl = g_Wvlo; C = g_V; }
    gemm_core(g_xhi, g_xlo, Bh, Bl, C, nullptr, nullptr, HIDN, HIDN,
              blockIdx.y * 128, colb * 128, which == 0, 0);
}

// ================ transpose V -> split bf16 VT[bh][dv][t] ================
__global__ __launch_bounds__(256)
void transpose_v() {
    __shared__ float tile[32][33];
    const int ttile = blockIdx.x;            // 0..63
    const int dvt = blockIdx.y & 3, bh = blockIdx.y >> 2;
    const int b = bh >> 3, h = bh & 7;
    const int t0 = ttile * 32, dv0 = dvt * 32;
    const int lx = threadIdx.x & 31, ly = threadIdx.x >> 5;   // ly 0..7
#pragma unroll
    for (int i = 0; i < 4; i++) {
        int r = ly + i * 8;   // t offset within tile
        tile[r][lx] = g_V[(size_t)(b * TT + t0 + r) * HIDN + h * DKK + dv0 + lx];
    }
    __syncthreads();
#pragma unroll
    for (int i = 0; i < 4; i++) {
        int r = ly + i * 8;   // dv offset within tile
        float v = tile[lx][r];           // = V[t0+lx][dv0+r]
        bf16 hh = __float2bfloat16_rn(v);
        bf16 ll = __float2bfloat16_rn(v - __bfloat162float(hh));
        size_t oa = ((size_t)bh * DKK + dv0 + r) * TT + t0 + lx;
        g_VThi[oa] = hh;
        g_VTlo[oa] = ll;
    }
}

// ================= attention kernels ==================
#define MICRO_FMA(Aptr, Bptr, kk) do {                                    \
    float4 a0 = *(const float4*)&(Aptr)[(kk)*132 + ty*4];                 \
    float4 a1 = *(const float4*)&(Aptr)[(kk)*132 + 64 + ty*4];            \
    float4 b0 = *(const float4*)&(Bptr)[(kk)*132 + tx*4];                 \
    float4 b1 = *(const float4*)&(Bptr)[(kk)*132 + 64 + tx*4];            \
    float av[8] = {a0.x,a0.y,a0.z,a0.w,a1.x,a1.y,a1.z,a1.w};              \
    float bv[8] = {b0.x,b0.y,b0.z,b0.w,b1.x,b1.y,b1.z,b1.w};              \
    _Pragma("unroll") for (int ii=0; ii<8; ii++)                          \
      _Pragma("unroll") for (int jj=0; jj<8; jj++)                        \
        acc[ii][jj] += av[ii]*bv[jj];                                     \
} while(0)

__device__ __forceinline__ int fragmap(int idx, int t4) {
    return (idx < 4) ? (t4*4 + idx) : (64 + t4*4 + idx - 4);
}

// exp(k) in place (+split bf16 out), per-chunk colsum, CcT = V^T EK (fp32)
__global__ __launch_bounds__(256)
void chunk_stats() {
    const int c = blockIdx.x, bh = blockIdx.y;
    const int b = bh >> 3, h = bh & 7;
    const int base = b*TT + c*TCH;
    const int hoff = h*DKK;
    __shared__ float EKs[8*132];
    __shared__ float Vs[8*132];
    __shared__ float red[8*128];
    const int tid = threadIdx.x;
    const int tx = tid & 15, ty = tid >> 4;
    const int trow = tid >> 5;
    const int col = (tid & 31) << 2;
    float acc[8][8];
#pragma unroll
    for (int i = 0; i < 8; i++)
#pragma unroll
        for (int j = 0; j < 8; j++) acc[i][j] = 0.f;
    float ps0 = 0.f, ps1 = 0.f, ps2 = 0.f, ps3 = 0.f;

    for (int tt = 0; tt < TCH/8; tt++) {
        int row = base + tt*8 + trow;
        size_t gi = (size_t)row*HIDN + hoff + col;
        float4 kv = *(const float4*)(g_EK + gi);
        kv.x = expf(kv.x); kv.y = expf(kv.y); kv.z = expf(kv.z); kv.w = expf(kv.w);
        *(float4*)(g_EK + gi) = kv;
        uint32_t h0, l0, h1, l1;
        split2(kv.x, kv.y, h0, l0);
        split2(kv.z, kv.w, h1, l1);
        uint2 hu; hu.x = h0; hu.y = h1;
        uint2 lu; lu.x = l0; lu.y = l1;
        *(uint2*)(g_EKhi + gi) = hu;
        *(uint2*)(g_EKlo + gi) = lu;
        ps0 += kv.x; ps1 += kv.y; ps2 += kv.z; ps3 += kv.w;
        *(float4*)&EKs[trow*132 + col] = kv;
        float4 vv = *(const float4*)(g_V + gi);
        *(float4*)&Vs[trow*132 + col] = vv;
        __syncthreads();
#pragma unroll
        for (int k = 0; k < 8; k++) MICRO_FMA(Vs, EKs, k);   // acc[dv][dk] = CcT
        __syncthreads();
    }
    red[trow*128 + col + 0] = ps0; red[trow*128 + col + 1] = ps1;
    red[trow*128 + col + 2] = ps2; red[trow*128 + col + 3] = ps3;
    __syncthreads();
    if (tid < DKK) {
        float s = 0.f;
#pragma unroll
        for (int r = 0; r < 8; r++) s += red[r*128 + tid];
        g_Asum[(bh*NCHUNK + c)*DKK + tid] = s;
    }
    size_t cb = ((size_t)(bh*NCHUNK + c))*DKK*DKK;
#pragma unroll
    for (int i = 0; i < 8; i++) {
        int dv = fragmap(i, ty);
        float4 s0 = make_float4(acc[i][0], acc[i][1], acc[i][2], acc[i][3]);
        float4 s1 = make_float4(acc[i][4], acc[i][5], acc[i][6], acc[i][7]);
        *(float4*)(g_CcT + cb + (size_t)dv*DKK + tx*4)      = s0;
        *(float4*)(g_CcT + cb + (size_t)dv*DKK + 64 + tx*4) = s1;
    }
}

__global__ void scan_asum() {
    int bh = blockIdx.x, dk = threadIdx.x;
    float run = 0.f;
    for (int c = 0; c < NCHUNK; c++) {
        int i = (bh*NCHUNK + c)*DKK + dk;
        float v = g_Asum[i]; g_Asum[i] = run; run += v;
    }
}
// exclusive prefix of CcT across chunks -> split bf16
__global__ void scan_cc() {
    int bh = blockIdx.y;
    int idx = blockIdx.x*256 + threadIdx.x;
    float run = 0.f;
    for (int c = 0; c < NCHUNK; c++) {
        size_t p = ((size_t)(bh*NCHUNK + c))*(DKK*DKK) + idx;
        float v = g_CcT[p];
        bf16 hh = __float2bfloat16_rn(run);
        bf16 ll = __float2bfloat16_rn(run - __bfloat162float(hh));
        g_CcThi[p] = hh; g_CcTlo[p] = ll;
        run += v;
    }
}

// Qhat = silu(q)/A_t * scale -> split bf16
__global__ void compute_qhat() {
    const int c = blockIdx.x, bh = blockIdx.y;
    const int b = bh >> 3, h = bh & 7;
    const int base = b*TT + c*TCH;
    const int dk = threadIdx.x;
    const float scale = 0.08838834764831845f;
    float run = g_Asum[(bh*NCHUNK + c)*DKK + dk];
    for (int t = 0; t < TCH; t++) {
        size_t gi = (size_t)(base + t)*HIDN + h*DKK + dk;
        run += g_EK[gi];
        float qh = g_Q[gi] / run * scale;
        bf16 hh = __float2bfloat16_rn(qh);
        bf16 ll = __float2bfloat16_rn(qh - __bfloat162float(hh));
        g_QHhi[gi] = hh; g_QHlo[gi] = ll;
    }
}

// ====== chunk_out (tensor core): O = tril(QH EK^T) V + QH Cc ======
// smem: QH hi/lo @0/32K, B-slot hi/lo @64K/96K (EK then CcT then ...), P hi/lo @128K/160K
#define CO2_SMEM (6*32768 + 1024)

__device__ __forceinline__ void load_op(uint32_t shi, uint32_t slo,
        const bf16* __restrict__ ghi, const bf16* __restrict__ glo,
        size_t rstride, int tid) {
#pragma unroll
    for (int t = 0; t < 8; t++) {
        int idx = t * 256 + tid;
        int r = idx >> 4;
        int c16 = idx & 15;
        uint32_t off = (uint32_t)((c16 >> 3) * 16384) + SMEM_SWZ((uint32_t)(r * 128 + (c16 & 7) * 16));
        CP_ASYNC16(shi + off, ghi + (size_t)r * rstride + c16 * 8);
        CP_ASYNC16(slo + off, glo + (size_t)r * rstride + c16 * 8);
    }
}

__global__ __launch_bounds__(256, 1)
void chunk_out_tc() {
    extern __shared__ char dynsm[];
    char* smb = (char*)((((uintptr_t)dynsm) + 1023) & ~(uintptr_t)1023);
    const uint32_t sa = smem_u32(smb);
    const int c = blockIdx.x, bh = blockIdx.y;
    const int b = bh >> 3, h = bh & 7;
    const int tbase = b*TT + c*TCH;
    const int hoff = h*DKK;
    const int tid = threadIdx.x, wid = tid >> 5, l = tid & 31;
    const int warp_m = wid >> 1, warp_n = wid & 1;
    const int a_row = warp_m * 32 + (l & 15);
    const int a_kb  = (l >> 4) * 16;
    const int b_row = warp_n * 64 + (l & 7) + ((l >> 4) & 1) * 8;
    const int b_kb  = ((l >> 3) & 1) * 16;

    const uint32_t QHI = sa, QLO = sa + 32768;
    const uint32_t BHI = sa + 65536, BLO = sa + 98304;
    const uint32_t PHI = sa + 131072, PLO = sa + 163840;
    char* Pc_hi = smb + 131072;
    char* Pc_lo = smb + 163840;

    // load QH + EK tiles
    load_op(QHI, QLO, g_QHhi + (size_t)tbase*HIDN + hoff, g_QHlo + (size_t)tbase*HIDN + hoff, HIDN, tid);
    load_op(BHI, BLO, g_EKhi + (size_t)tbase*HIDN + hoff, g_EKlo + (size_t)tbase*HIDN + hoff, HIDN, tid);
    CP_COMMIT(); CP_WAIT0(); __syncthreads();

    float acc[2][8][4];
#pragma unroll
    for (int mf = 0; mf < 2; mf++)
#pragma unroll
        for (int nf = 0; nf < 8; nf++)
#pragma unroll
            for (int j = 0; j < 4; j++) acc[mf][nf][j] = 0.f;

    // stage 1: P = QH * EK^T  (K = dk = 128)
#pragma unroll
    for (int kc = 0; kc < 2; kc++)
        mma_block64(acc, QHI + kc*16384, QLO + kc*16384, BHI + kc*16384, BLO + kc*16384,
                    a_row, a_kb, b_row, b_kb);
    __syncthreads();   // all warps done reading EK slot

    // overlap: start loading CcT into B slot while storing masked P
    load_op(BHI, BLO, g_CcThi + (size_t)(bh*NCHUNK + c)*(DKK*DKK),
                       g_CcTlo + (size_t)(bh*NCHUNK + c)*(DKK*DKK), DKK, tid);
    CP_COMMIT();

    // causal mask + store P to smem (split bf16), row-major [t][s] in 2x64 chunk layout
#pragma unroll
    for (int mf = 0; mf < 2; mf++)
#pragma unroll
        for (int nf = 0; nf < 8; nf++) {
            int r0 = warp_m * 32 + mf * 16 + (l >> 2);
            int cc = warp_n * 64 + nf * 8 + (l & 3) * 2;
            float v0 = (cc     <= r0) ? acc[mf][nf][0] : 0.f;
            float v1 = (cc + 1 <= r0) ? acc[mf][nf][1] : 0.f;
            float v2 = (cc     <= r0 + 8) ? acc[mf][nf][2] : 0.f;
            float v3 = (cc + 1 <= r0 + 8) ? acc[mf][nf][3] : 0.f;
            uint32_t ch = (uint32_t)((cc >> 6) * 16384);
            uint32_t o0 = ch + SMEM_SWZ((uint32_t)(r0 * 128 + (cc & 63) * 2));
            uint32_t o1 = ch + SMEM_SWZ((uint32_t)((r0 + 8) * 128 + (cc & 63) * 2));
            uint32_t hh, ll;
            split2(v0, v1, hh, ll);
            *(uint32_t*)(Pc_hi + o0) = hh; *(uint32_t*)(Pc_lo + o0) = ll;
            split2(v2, v3, hh, ll);
            *(uint32_t*)(Pc_hi + o1) = hh; *(uint32_t*)(Pc_lo + o1) = ll;
        }
    CP_WAIT0(); __syncthreads();   // P visible, CcT loaded

    // stage 2b: O = QH * CcT^T   (K = dk)
#pragma unroll
    for (int mf = 0; mf < 2; mf++)
#pragma unroll
        for (int nf = 0; nf < 8; nf++)
#pragma unroll
            for (int j = 0; j < 4; j++) acc[mf][nf][j] = 0.f;
#pragma unroll
    for (int kc = 0; kc < 2; kc++)
        mma_block64(acc, QHI + kc*16384, QLO + kc*16384, BHI + kc*16384, BLO + kc*16384,
                    a_row, a_kb, b_row, b_kb);
    __syncthreads();   // done reading QH slot

    // load VT into QH slot
    load_op(QHI, QLO, g_VThi + (size_t)bh*DKK*TT + c*TCH,
                       g_VTlo + (size_t)bh*DKK*TT + c*TCH, TT, tid);
    CP_COMMIT(); CP_WAIT0(); __syncthreads();

    // stage 2a: O += P * VT^T   (K = s)
#pragma unroll
    for (int kc = 0; kc < 2; kc++)
        mma_block64(acc, PHI + kc*16384, PLO + kc*16384, QHI + kc*16384, QLO + kc*16384,
                    a_row, a_kb, b_row, b_kb);

    // write O fp32
#pragma unroll
    for (int mf = 0; mf < 2; mf++)
#pragma unroll
        for (int nf = 0; nf < 8; nf++) {
            int r0 = warp_m * 32 + mf * 16 + (l >> 2);
            int cc = warp_n * 64 + nf * 8 + (l & 3) * 2;
            *(float2*)(g_O + (size_t)(tbase + r0) * HIDN + hoff + cc) =
                make_float2(acc[mf][nf][0], acc[mf][nf][1]);
            *(float2*)(g_O + (size_t)(tbase + r0 + 8) * HIDN + hoff + cc) =
                make_float2(acc[mf][nf][2], acc[mf][nf][3]);
        }
}

// epilogue: RMSNorm(o) * w * gate * sigmoid(gate) -> split bf16 U
__global__ __launch_bounds__(256)
void epilogue_k(const float* __restrict__ gnw) {
    __shared__ float red[256];
    const int n = blockIdx.x, tid = threadIdx.x;
    float4 ov = *((const float4*)(g_O + (size_t)n*HIDN) + tid);
    float ss = ov.x*ov.x + ov.y*ov.y + ov.z*ov.z + ov.w*ov.w;
    red[tid] = ss;
    __syncthreads();
    for (int s = 128; s > 0; s >>= 1) {
        if (tid < s) red[tid] += red[tid + s];
        __syncthreads();
    }
    float rms = rsqrtf(red[0] * (1.f/HIDN) + 1e-5f);
    float4 gv = *((const float4*)(g_gate + (size_t)n*HIDN) + tid);
    float4 wv = *((const float4*)gnw + tid);
    float4 u;
    u.x = ov.x*rms*wv.x * gv.x / (1.f + expf(-gv.x));
    u.y = ov.y*rms*wv.y * gv.y / (1.f + expf(-gv.y));
    u.z = ov.z*rms*wv.z * gv.z / (1.f + expf(-gv.z));
    u.w = ov.w*rms*wv.w * gv.w / (1.f + expf(-gv.w));
    size_t off = (size_t)n*HIDN + tid*4;
    store_pair_split(g_Uhi, g_Ulo, off, u.x, u.y);
    store_pair_split(g_Uhi, g_Ulo, off + 2, u.z, u.w);
}

extern "C" void kernel_launch(void* const* d_in, const int* in_sizes, int n_in,
                              void* d_out, int out_size) {
    const float* x   = (const float*)d_in[0];
    const float* Wq  = (const float*)d_in[1];
    const float* Wk  = (const float*)d_in[2];
    const float* Wv  = (const float*)d_in[3];
    const float* Wg1 = (const float*)d_in[4];
    const float* Wg2 = (const float*)d_in[5];
    const float* gnw = (const float*)d_in[6];
    const float* Wo  = (const float*)d_in[7];
    float* out = (float*)d_out;

    bf16 *xhi,*xlo,*wqh,*wql,*wkh,*wkl,*wvh,*wvl,*woh,*wol,*w1h,*w1l,*w2h,*w2l,*g1h,*g1l,*uh,*ul;
    float* gate;
    cudaGetSymbolAddress((void**)&xhi, g_xhi);  cudaGetSymbolAddress((void**)&xlo, g_xlo);
    cudaGetSymbolAddress((void**)&wqh, g_Wqhi); cudaGetSymbolAddress((void**)&wql, g_Wqlo);
    cudaGetSymbolAddress((void**)&wkh, g_Wkhi); cudaGetSymbolAddress((void**)&wkl, g_Wklo);
    cudaGetSymbolAddress((void**)&wvh, g_Wvhi); cudaGetSymbolAddress((void**)&wvl, g_Wvlo);
    cudaGetSymbolAddress((void**)&woh, g_Wohi); cudaGetSymbolAddress((void**)&wol, g_Wolo);
    cudaGetSymbolAddress((void**)&w1h, g_Wg1hi); cudaGetSymbolAddress((void**)&w1l, g_Wg1lo);
    cudaGetSymbolAddress((void**)&w2h, g_Wg2hi); cudaGetSymbolAddress((void**)&w2l, g_Wg2lo);
    cudaGetSymbolAddress((void**)&g1h, g_G1hi); cudaGetSymbolAddress((void**)&g1l, g_G1lo);
    cudaGetSymbolAddress((void**)&uh, g_Uhi);   cudaGetSymbolAddress((void**)&ul, g_Ulo);
    cudaGetSymbolAddress((void**)&gate, g_gate);

    cudaFuncSetAttribute(gemm_qkv, cudaFuncAttributeMaxDynamicSharedMemorySize, GEMM_SMEM);
    cudaFuncSetAttribute(gemm_bf16<0,0>, cudaFuncAttributeMaxDynamicSharedMemorySize, GEMM_SMEM);
    cudaFuncSetAttribute(gemm_bf16<0,1>, cudaFuncAttributeMaxDynamicSharedMemorySize, GEMM_SMEM);
    cudaFuncSetAttribute(chunk_out_tc, cudaFuncAttributeMaxDynamicSharedMemorySize, CO2_SMEM);

    dim3 blk(256);
    // ordered so launch #6 = gemm_qkv (for ncu -s 5 -c 1)
    convert_split<<<NROWS*HIDN/1024, blk>>>(x, xhi, xlo, NROWS*HIDN);         // 1
    convert_split<<<HIDN*HIDN/1024, blk>>>(Wq, wqh, wql, HIDN*HIDN);          // 2
    convert_split<<<HIDN*HIDN/1024, blk>>>(Wk, wkh, wkl, HIDN*HIDN);          // 3
    convert_split<<<HIDN*HIDN/1024, blk>>>(Wv, wvh, wvl, HIDN*HIDN);          // 4
    convert_split<<<128*HIDN/1024, blk>>>(Wg1, w1h, w1l, 128*HIDN);           // 5
    gemm_qkv<<<dim3(24,32), blk, GEMM_SMEM>>>();                              // 6 <- profiled
    gemm_bf16<0,1><<<dim3(1,32), blk, GEMM_SMEM>>>(xhi, xlo, w1h, w1l, nullptr, g1h, g1l, 128, HIDN); // 7
    convert_split<<<HIDN*128/1024, blk>>>(Wg2, w2h, w2l, HIDN*128);           // 8
    gemm_bf16<0,0><<<dim3(8,32), blk, GEMM_SMEM>>>(g1h, g1l, w2h, w2l, gate, nullptr, nullptr, HIDN, 128); // 9
    convert_split<<<HIDN*HIDN/1024, blk>>>(Wo, woh, wol, HIDN*HIDN);          // 10
    chunk_stats<<<dim3(NCHUNK, NBH), blk>>>();                                // 11
    scan_asum<<<NBH, DKK>>>();                                                // 12
    scan_cc<<<dim3(64, NBH), 256>>>();                                        // 13
    transpose_v<<<dim3(64, 4*NBH), blk>>>();                                  // 14
    compute_qhat<<<dim3(NCHUNK, NBH), DKK>>>();                               // 15
    chunk_out_tc<<<dim3(NCHUNK, NBH), blk, CO2_SMEM>>>();                     // 16
    epilogue_k<<<NROWS, blk>>>(gnw);                                          // 17
    gemm_bf16<0,0><<<dim3(8,32), blk, GEMM_SMEM>>>(uh, ul, woh, wol, out, nullptr, nullptr, HIDN, HIDN); // 18
}